// round 3
// baseline (speedup 1.0000x reference)
#include <cuda_runtime.h>
#include <cuda_bf16.h>
#include <cstdint>

#define N_NODES 50000
#define N_EDGES 800000
#define IN_CH 256
#define HID 256
#define OUT_CH 128
#define N_GRAPHS 64

// ---------------- scratch (device globals; no cudaMalloc allowed) ----------
__device__ float g_deg[N_NODES];
__device__ float g_dinv[N_NODES];
__device__ float g_h1[(size_t)N_NODES * HID];
__device__ float g_buf1[(size_t)N_NODES * HID];   // agg1, then out1 in place
__device__ float g_h2[(size_t)N_NODES * OUT_CH];
__device__ float g_agg2[(size_t)N_NODES * OUT_CH];
__device__ float g_sums[N_GRAPHS * OUT_CH];
__device__ int   g_counts[N_GRAPHS];
__device__ int   g_src[N_EDGES];
__device__ int   g_dst[N_EDGES];
__device__ int   g_batch[N_NODES];
__device__ int   g_odd_ei;    // nonzero-odd-dword count for edge_index
__device__ int   g_odd_bat;   // nonzero-odd-dword count for batch

// ---------------- helpers ---------------------------------------------------
__device__ __forceinline__ void red_add_v4(float* addr, float4 v) {
    asm volatile("red.global.add.v4.f32 [%0], {%1,%2,%3,%4};"
                 :: "l"(addr), "f"(v.x), "f"(v.y), "f"(v.z), "f"(v.w)
                 : "memory");
}

// ---------------- dtype detection -------------------------------------------
// View buffer as int32. If true dtype is int64 (values < 2^31), odd dwords are 0.
// If int32, odd dwords are real indices (almost all nonzero). nelem32 = count of
// int32 slots that are safe to read under EITHER interpretation.
__global__ void detect_kernel(const int* __restrict__ buf32, int nelem32, int* cnt) {
    int i = blockIdx.x * blockDim.x + threadIdx.x;
    int local = 0;
    if (2 * i + 1 < nelem32 && buf32[2 * i + 1] != 0) local = 1;
    // warp-aggregate to cut atomic traffic
    unsigned m = __ballot_sync(0xFFFFFFFFu, local);
    if ((threadIdx.x & 31) == 0 && m) atomicAdd(cnt, __popc(m));
}

__global__ void conv_ei_kernel(const void* __restrict__ ei, int* __restrict__ src,
                               int* __restrict__ dst, const int* __restrict__ cnt) {
    int e = blockIdx.x * blockDim.x + threadIdx.x;
    if (e >= N_EDGES) return;
    int s, d;
    if (*cnt < 100) {   // int64
        const long long* p = (const long long*)ei;
        s = (int)p[e];  d = (int)p[N_EDGES + e];
    } else {            // int32
        const int* p = (const int*)ei;
        s = p[e];  d = p[N_EDGES + e];
    }
    src[e] = min(max(s, 0), N_NODES - 1);
    dst[e] = min(max(d, 0), N_NODES - 1);
}

__global__ void conv_bat_kernel(const void* __restrict__ bat, int* __restrict__ out,
                                const int* __restrict__ cnt) {
    int i = blockIdx.x * blockDim.x + threadIdx.x;
    if (i >= N_NODES) return;
    int g;
    if (*cnt < 100) g = (int)((const long long*)bat)[i];
    else            g = ((const int*)bat)[i];
    out[i] = min(max(g, 0), N_GRAPHS - 1);
}

// ---------------- degree ----------------------------------------------------
__global__ void deg_kernel(const int* __restrict__ dst, float* __restrict__ deg) {
    int e = blockIdx.x * blockDim.x + threadIdx.x;
    if (e < N_EDGES) atomicAdd(&deg[dst[e]], 1.0f);
}

__global__ void dinv_kernel(const float* __restrict__ deg, float* __restrict__ dinv) {
    int i = blockIdx.x * blockDim.x + threadIdx.x;
    if (i < N_NODES) dinv[i] = rsqrtf(deg[i] + 1.0f);
}

// ---------------- classic fp32 tiled GEMM: C[M,N] = A[M,K] @ B[K,N] ---------
#define BM 64
#define BN 64
#define BK 16
#define TM 4
#define TN 4
__global__ __launch_bounds__(256) void sgemm_kernel(
    int M, int N, int K,
    const float* __restrict__ A, const float* __restrict__ B, float* __restrict__ C)
{
    __shared__ float As[BK][BM];
    __shared__ float Bs[BK][BN];

    const int bm = blockIdx.y * BM;
    const int bn = blockIdx.x * BN;
    const int tid = threadIdx.x;
    const int tx = tid % 16;
    const int ty = tid / 16;

    const int arow  = tid >> 2;
    const int acol4 = (tid & 3) * 4;
    const int brow  = tid >> 4;
    const int bcol4 = (tid & 15) * 4;

    float acc[TM][TN];
    #pragma unroll
    for (int i = 0; i < TM; i++)
        #pragma unroll
        for (int j = 0; j < TN; j++) acc[i][j] = 0.0f;

    for (int k0 = 0; k0 < K; k0 += BK) {
        float4 av = make_float4(0.f, 0.f, 0.f, 0.f);
        int gr = bm + arow;
        if (gr < M) av = *(const float4*)(A + (size_t)gr * K + k0 + acol4);
        As[acol4 + 0][arow] = av.x;
        As[acol4 + 1][arow] = av.y;
        As[acol4 + 2][arow] = av.z;
        As[acol4 + 3][arow] = av.w;

        float4 bv = *(const float4*)(B + (size_t)(k0 + brow) * N + bn + bcol4);
        *(float4*)&Bs[brow][bcol4] = bv;
        __syncthreads();

        #pragma unroll
        for (int k = 0; k < BK; k++) {
            float am[TM], bb[TN];
            #pragma unroll
            for (int i = 0; i < TM; i++) am[i] = As[k][ty * TM + i];
            #pragma unroll
            for (int j = 0; j < TN; j++) bb[j] = Bs[k][tx * TN + j];
            #pragma unroll
            for (int i = 0; i < TM; i++)
                #pragma unroll
                for (int j = 0; j < TN; j++) acc[i][j] = fmaf(am[i], bb[j], acc[i][j]);
        }
        __syncthreads();
    }

    #pragma unroll
    for (int i = 0; i < TM; i++) {
        int r = bm + ty * TM + i;
        if (r < M) {
            float4 v = make_float4(acc[i][0], acc[i][1], acc[i][2], acc[i][3]);
            *(float4*)(C + (size_t)r * N + bn + tx * TN) = v;
        }
    }
}

// ---------------- edge scatter: agg[dst] += h[src] * dinv[src]*dinv[dst] ----
template <int F>
__global__ void edge_agg_kernel(const int* __restrict__ src_arr,
                                const int* __restrict__ dst_arr,
                                const float* __restrict__ dinv,
                                const float* __restrict__ h,
                                float* __restrict__ agg)
{
    int e    = blockIdx.x * (blockDim.x >> 5) + (threadIdx.x >> 5);
    int lane = threadIdx.x & 31;
    if (e >= N_EDGES) return;

    int s = src_arr[e];
    int d = dst_arr[e];
    float nrm = dinv[s] * dinv[d];

    const float4* hr = (const float4*)(h + (size_t)s * F);
    float* ar = agg + (size_t)d * F;

    #pragma unroll
    for (int c = lane; c < F / 4; c += 32) {
        float4 v = __ldg(hr + c);
        v.x *= nrm; v.y *= nrm; v.z *= nrm; v.w *= nrm;
        red_add_v4(ar + c * 4, v);
    }
}

// ---------------- finalize layer1: buf = ELU(agg + h*(1/deg) + b) -----------
__global__ void finalize1_kernel(const float* __restrict__ h1,
                                 float* __restrict__ buf,
                                 const float* __restrict__ b1,
                                 const float* __restrict__ dinv)
{
    size_t idx = (size_t)blockIdx.x * blockDim.x + threadIdx.x;   // float4 units
    size_t total = (size_t)N_NODES * HID / 4;
    if (idx >= total) return;
    int row = (int)(idx * 4 / HID);
    int col = (int)(idx * 4 % HID);

    float id = dinv[row];
    float sl = id * id;   // 1/deg

    float4 a = ((const float4*)buf)[idx];
    float4 h = ((const float4*)h1)[idx];
    float4 b = *(const float4*)(b1 + col);

    float v[4] = { a.x + h.x * sl + b.x,
                   a.y + h.y * sl + b.y,
                   a.z + h.z * sl + b.z,
                   a.w + h.w * sl + b.w };
    #pragma unroll
    for (int i = 0; i < 4; i++) v[i] = v[i] > 0.0f ? v[i] : expm1f(v[i]);

    ((float4*)buf)[idx] = make_float4(v[0], v[1], v[2], v[3]);
}

// ---------------- finalize layer2 + mean-pool accumulation ------------------
__global__ void fin2_pool_kernel(const float* __restrict__ h2,
                                 const float* __restrict__ agg2,
                                 const float* __restrict__ b2,
                                 const float* __restrict__ dinv,
                                 const int* __restrict__ batch,
                                 float* __restrict__ sums,
                                 int* __restrict__ counts)
{
    int node = blockIdx.x * (blockDim.x >> 5) + (threadIdx.x >> 5);
    int lane = threadIdx.x & 31;
    if (node >= N_NODES) return;

    float id = dinv[node];
    float sl = id * id;
    int g = batch[node];

    float4 a = ((const float4*)(agg2 + (size_t)node * OUT_CH))[lane];
    float4 h = ((const float4*)(h2   + (size_t)node * OUT_CH))[lane];
    float4 b = ((const float4*)b2)[lane];

    float4 v = make_float4(a.x + h.x * sl + b.x,
                           a.y + h.y * sl + b.y,
                           a.z + h.z * sl + b.z,
                           a.w + h.w * sl + b.w);
    red_add_v4(sums + g * OUT_CH + lane * 4, v);
    if (lane == 0) atomicAdd(&counts[g], 1);
}

__global__ void pool_final_kernel(const float* __restrict__ sums,
                                  const int* __restrict__ counts,
                                  float* __restrict__ out)
{
    int c = blockIdx.x * blockDim.x + threadIdx.x;
    if (c < N_GRAPHS * OUT_CH) {
        int g = c / OUT_CH;
        float cnt = fmaxf((float)counts[g], 1.0f);
        out[c] = sums[c] / cnt;
    }
}

__global__ void zero_out_kernel(float* out, int n) {
    int i = blockIdx.x * blockDim.x + threadIdx.x;
    if (i < n) out[i] = 0.0f;
}

// ---------------- launch -----------------------------------------------------
extern "C" void kernel_launch(void* const* d_in, const int* in_sizes, int n_in,
                              void* d_out, int out_size)
{
    // Identify inputs by UNIQUE element counts (robust to metadata ordering):
    //   x: 12,800,000  W1: 65,536  b1: 256  W2: 32,768  b2: 128
    //   edge_index: 1,600,000  batch: 50,000
    const float* x   = nullptr;
    const float* W1  = nullptr;
    const float* b1  = nullptr;
    const float* W2  = nullptr;
    const float* b2  = nullptr;
    const void*  ei  = nullptr;   // dtype detected on device
    const void*  bat = nullptr;

    for (int i = 0; i < n_in; i++) {
        switch (in_sizes[i]) {
            case 12800000: x   = (const float*)d_in[i]; break;
            case 65536:    W1  = (const float*)d_in[i]; break;
            case 256:      b1  = (const float*)d_in[i]; break;
            case 32768:    W2  = (const float*)d_in[i]; break;
            case 128:      b2  = (const float*)d_in[i]; break;
            case 1600000:  ei  = d_in[i];               break;
            case 50000:    bat = d_in[i];               break;
            default: break;
        }
    }
    float* out = (float*)d_out;

    if (!x || !W1 || !b1 || !W2 || !b2 || !ei || !bat) {
        // Defensive: never crash; produce zeros (fails rel_err, not IMA).
        zero_out_kernel<<<(out_size + 255) / 256, 256>>>(out, out_size);
        return;
    }

    void* p;
    cudaGetSymbolAddress(&p, g_deg);     float* deg    = (float*)p;
    cudaGetSymbolAddress(&p, g_dinv);    float* dinv   = (float*)p;
    cudaGetSymbolAddress(&p, g_h1);      float* h1     = (float*)p;
    cudaGetSymbolAddress(&p, g_buf1);    float* buf1   = (float*)p;
    cudaGetSymbolAddress(&p, g_h2);      float* h2     = (float*)p;
    cudaGetSymbolAddress(&p, g_agg2);    float* agg2   = (float*)p;
    cudaGetSymbolAddress(&p, g_sums);    float* sums   = (float*)p;
    cudaGetSymbolAddress(&p, g_counts);  int*   counts = (int*)p;
    cudaGetSymbolAddress(&p, g_src);     int*   src    = (int*)p;
    cudaGetSymbolAddress(&p, g_dst);     int*   dst    = (int*)p;
    cudaGetSymbolAddress(&p, g_batch);   int*   batch  = (int*)p;
    cudaGetSymbolAddress(&p, g_odd_ei);  int*   oddei  = (int*)p;
    cudaGetSymbolAddress(&p, g_odd_bat); int*   oddbat = (int*)p;

    cudaMemsetAsync(deg,    0, N_NODES * sizeof(float));
    cudaMemsetAsync(buf1,   0, (size_t)N_NODES * HID * sizeof(float));
    cudaMemsetAsync(agg2,   0, (size_t)N_NODES * OUT_CH * sizeof(float));
    cudaMemsetAsync(sums,   0, N_GRAPHS * OUT_CH * sizeof(float));
    cudaMemsetAsync(counts, 0, N_GRAPHS * sizeof(int));
    cudaMemsetAsync(oddei,  0, sizeof(int));
    cudaMemsetAsync(oddbat, 0, sizeof(int));

    // dtype detection: int32 view is a safe-size read for either dtype.
    detect_kernel<<<(1600000 / 2 + 255) / 256, 256>>>((const int*)ei, 1600000, oddei);
    detect_kernel<<<(50000 / 2 + 255) / 256, 256>>>((const int*)bat, 50000, oddbat);

    conv_ei_kernel<<<(N_EDGES + 255) / 256, 256>>>(ei, src, dst, oddei);
    conv_bat_kernel<<<(N_NODES + 255) / 256, 256>>>(bat, batch, oddbat);

    deg_kernel<<<(N_EDGES + 255) / 256, 256>>>(dst, deg);
    dinv_kernel<<<(N_NODES + 255) / 256, 256>>>(deg, dinv);

    // h1 = x @ W1
    sgemm_kernel<<<dim3(HID / BN, (N_NODES + BM - 1) / BM), 256>>>(
        N_NODES, HID, IN_CH, x, W1, h1);

    // scatter layer 1
    edge_agg_kernel<HID><<<(N_EDGES + 7) / 8, 256>>>(src, dst, dinv, h1, buf1);

    // ELU(agg + h/deg + b1) in place
    {
        size_t total4 = (size_t)N_NODES * HID / 4;
        finalize1_kernel<<<(unsigned)((total4 + 255) / 256), 256>>>(h1, buf1, b1, dinv);
    }

    // h2 = out1 @ W2
    sgemm_kernel<<<dim3(OUT_CH / BN, (N_NODES + BM - 1) / BM), 256>>>(
        N_NODES, OUT_CH, HID, buf1, W2, h2);

    // scatter layer 2
    edge_agg_kernel<OUT_CH><<<(N_EDGES + 7) / 8, 256>>>(src, dst, dinv, h2, agg2);

    // finalize layer 2 + pool accumulation
    fin2_pool_kernel<<<(N_NODES + 7) / 8, 256>>>(h2, agg2, b2, dinv, batch, sums, counts);

    pool_final_kernel<<<(N_GRAPHS * OUT_CH + 255) / 256, 256>>>(sums, counts, out);
}

// round 5
// speedup vs baseline: 1.1812x; 1.1812x over previous
#include <cuda_runtime.h>
#include <cuda_bf16.h>
#include <cstdint>

#define N_NODES 50000
#define N_PAD   50048      // multiple of 128 for MMA tiles
#define N_EDGES 800000
#define IN_CH 256
#define HID 256
#define OUT_CH 128
#define N_GRAPHS 64

// ---------------- scratch (device globals; no cudaMalloc allowed) ----------
__device__ float g_deg[N_NODES];
__device__ float g_dinv[N_NODES];
__device__ float g_h1[(size_t)N_PAD * HID];
__device__ float g_buf1[(size_t)N_NODES * HID];
__device__ float g_h2[(size_t)N_PAD * OUT_CH];
__device__ float g_agg2[(size_t)N_NODES * OUT_CH];
__device__ float g_sums[N_GRAPHS * OUT_CH];
__device__ int   g_counts[N_GRAPHS];
__device__ int   g_src[N_EDGES];
__device__ int   g_dst[N_EDGES];
__device__ int   g_batch[N_NODES];
__device__ int   g_odd_ei;
__device__ int   g_odd_bat;
// bf16 split operands. Pad rows (>= N_NODES) stay zero: zero-initialized
// device globals, never written.
__device__ __nv_bfloat16 g_x_hi[(size_t)N_PAD * IN_CH];
__device__ __nv_bfloat16 g_x_lo[(size_t)N_PAD * IN_CH];
__device__ __nv_bfloat16 g_a2_hi[(size_t)N_PAD * HID];
__device__ __nv_bfloat16 g_a2_lo[(size_t)N_PAD * HID];
__device__ __nv_bfloat16 g_w1t_hi[HID * IN_CH];     // [n][k] = W1[k][n]
__device__ __nv_bfloat16 g_w1t_lo[HID * IN_CH];
__device__ __nv_bfloat16 g_w2t_hi[OUT_CH * HID];
__device__ __nv_bfloat16 g_w2t_lo[OUT_CH * HID];

// ---------------- helpers ---------------------------------------------------
__device__ __forceinline__ void red_add_v4(float* addr, float4 v) {
    asm volatile("red.global.add.v4.f32 [%0], {%1,%2,%3,%4};"
                 :: "l"(addr), "f"(v.x), "f"(v.y), "f"(v.z), "f"(v.w) : "memory");
}
__device__ __forceinline__ void mma_bf16(float* c, uint32_t a0, uint32_t a1,
                                         uint32_t a2, uint32_t a3,
                                         uint32_t b0, uint32_t b1) {
    asm volatile("mma.sync.aligned.m16n8k16.row.col.f32.bf16.bf16.f32 "
                 "{%0,%1,%2,%3}, {%4,%5,%6,%7}, {%8,%9}, {%0,%1,%2,%3};"
                 : "+f"(c[0]), "+f"(c[1]), "+f"(c[2]), "+f"(c[3])
                 : "r"(a0), "r"(a1), "r"(a2), "r"(a3), "r"(b0), "r"(b1));
}

// ---------------- dtype detection / conversion ------------------------------
__global__ void detect_kernel(const int* __restrict__ buf32, int nelem32, int* cnt) {
    int i = blockIdx.x * blockDim.x + threadIdx.x;
    int local = 0;
    if (2 * i + 1 < nelem32 && buf32[2 * i + 1] != 0) local = 1;
    unsigned m = __ballot_sync(0xFFFFFFFFu, local);
    if ((threadIdx.x & 31) == 0 && m) atomicAdd(cnt, __popc(m));
}
__global__ void conv_ei_kernel(const void* __restrict__ ei, int* __restrict__ src,
                               int* __restrict__ dst, const int* __restrict__ cnt) {
    int e = blockIdx.x * blockDim.x + threadIdx.x;
    if (e >= N_EDGES) return;
    int s, d;
    if (*cnt < 100) { const long long* p = (const long long*)ei; s = (int)p[e]; d = (int)p[N_EDGES + e]; }
    else            { const int* p = (const int*)ei;             s = p[e];      d = p[N_EDGES + e]; }
    src[e] = min(max(s, 0), N_NODES - 1);
    dst[e] = min(max(d, 0), N_NODES - 1);
}
__global__ void conv_bat_kernel(const void* __restrict__ bat, int* __restrict__ out,
                                const int* __restrict__ cnt) {
    int i = blockIdx.x * blockDim.x + threadIdx.x;
    if (i >= N_NODES) return;
    int g;
    if (*cnt < 100) g = (int)((const long long*)bat)[i];
    else            g = ((const int*)bat)[i];
    out[i] = min(max(g, 0), N_GRAPHS - 1);
}

// ---------------- bf16 two-term splits ---------------------------------------
__global__ void split_x_kernel(const float* __restrict__ x,
                               __nv_bfloat16* __restrict__ hi,
                               __nv_bfloat16* __restrict__ lo) {
    size_t i = (size_t)blockIdx.x * blockDim.x + threadIdx.x;
    if (i >= (size_t)N_NODES * IN_CH) return;
    float v = x[i];
    __nv_bfloat16 h = __float2bfloat16(v);
    hi[i] = h;
    lo[i] = __float2bfloat16(v - __bfloat162float(h));
}
__global__ void split_w_kernel(const float* __restrict__ W, int K, int N,
                               __nv_bfloat16* __restrict__ hi,
                               __nv_bfloat16* __restrict__ lo) {
    int i = blockIdx.x * blockDim.x + threadIdx.x;   // over N*K, transposed out
    if (i >= N * K) return;
    int n = i / K, k = i % K;
    float v = W[(size_t)k * N + n];
    __nv_bfloat16 h = __float2bfloat16(v);
    hi[(size_t)n * K + k] = h;
    lo[(size_t)n * K + k] = __float2bfloat16(v - __bfloat162float(h));
}

// ---------------- degree ----------------------------------------------------
__global__ void deg_kernel(const int* __restrict__ dst, float* __restrict__ deg) {
    int e = blockIdx.x * blockDim.x + threadIdx.x;
    if (e < N_EDGES) atomicAdd(&deg[dst[e]], 1.0f);
}
__global__ void dinv_kernel(const float* __restrict__ deg, float* __restrict__ dinv) {
    int i = blockIdx.x * blockDim.x + threadIdx.x;
    if (i < N_NODES) dinv[i] = rsqrtf(deg[i] + 1.0f);
}

// ---------------- HMMA GEMM: C[Mpad,NT] = A[Mpad,256] @ Wt[NT,256]^T --------
// A, Wt given as bf16 (hi,lo) splits. 3-pass: hh + hl + lh, fp32 accumulate.
// CTA tile 128(M) x 64(N), BK=32. 256 threads = 8 warps in 4(M) x 2(N),
// each warp computes 32x32 via m16n8k16: 2 m-tiles x 4 n-tiles.
#define PADK 40   // smem k-stride in bf16 elems (32 data + 8 pad) -> conflict-free
template <int NT>
__global__ __launch_bounds__(256) void mma_gemm_kernel(
    const __nv_bfloat16* __restrict__ Ahi, const __nv_bfloat16* __restrict__ Alo,
    const __nv_bfloat16* __restrict__ Bhi, const __nv_bfloat16* __restrict__ Blo,
    float* __restrict__ C)
{
    constexpr int K = 256;
    __shared__ __align__(16) __nv_bfloat16 sAh[128 * PADK];
    __shared__ __align__(16) __nv_bfloat16 sAl[128 * PADK];
    __shared__ __align__(16) __nv_bfloat16 sBh[64 * PADK];
    __shared__ __align__(16) __nv_bfloat16 sBl[64 * PADK];

    const int tid  = threadIdx.x;
    const int lane = tid & 31;
    const int wid  = tid >> 5;
    const int wm   = wid & 3;          // 0..3 (M)
    const int wn   = wid >> 2;         // 0..1 (N)
    const int bm   = blockIdx.y * 128;
    const int bn   = blockIdx.x * 64;

    float acc[2][4][4];
    #pragma unroll
    for (int mt = 0; mt < 2; mt++)
        #pragma unroll
        for (int nt = 0; nt < 4; nt++)
            #pragma unroll
            for (int j = 0; j < 4; j++) acc[mt][nt][j] = 0.0f;

    const int qr = lane >> 2;          // 0..7  (row/col group within fragment)
    const int qc = (lane & 3) * 2;     // 0,2,4,6 (k pair)

    for (int kc = 0; kc < K; kc += 32) {
        // ---- load A chunk: 128 rows x 32 bf16 (hi & lo), 512 uint4 each ----
        #pragma unroll
        for (int t = tid; t < 512; t += 256) {
            int r = t >> 2, i = t & 3;
            size_t gi = (size_t)(bm + r) * K + kc + i * 8;
            *(uint4*)&sAh[r * PADK + i * 8] = *(const uint4*)(Ahi + gi);
            *(uint4*)&sAl[r * PADK + i * 8] = *(const uint4*)(Alo + gi);
        }
        // ---- load B chunk: 64 rows x 32 bf16 (hi & lo) ----
        {
            int t = tid;                       // 256 uint4 -> 1 per thread
            int r = t >> 2, i = t & 3;
            size_t gi = (size_t)(bn + r) * K + kc + i * 8;
            *(uint4*)&sBh[r * PADK + i * 8] = *(const uint4*)(Bhi + gi);
            *(uint4*)&sBl[r * PADK + i * 8] = *(const uint4*)(Blo + gi);
        }
        __syncthreads();

        #pragma unroll
        for (int ks = 0; ks < 2; ks++) {       // two k16 steps per 32-chunk
            const int kb = ks * 16;
            // A fragments (hi, lo) for both m-tiles
            uint32_t ah[2][4], al[2][4];
            #pragma unroll
            for (int mt = 0; mt < 2; mt++) {
                int r0 = wm * 32 + mt * 16 + qr;
                #pragma unroll
                for (int h = 0; h < 2; h++) {          // row, row+8
                    int r = r0 + h * 8;
                    ah[mt][h]     = *(const uint32_t*)&sAh[r * PADK + kb + qc];
                    ah[mt][h + 2] = *(const uint32_t*)&sAh[r * PADK + kb + qc + 8];
                    al[mt][h]     = *(const uint32_t*)&sAl[r * PADK + kb + qc];
                    al[mt][h + 2] = *(const uint32_t*)&sAl[r * PADK + kb + qc + 8];
                }
            }
            // B fragments (hi, lo) for 4 n-tiles
            uint32_t bh[4][2], bl[4][2];
            #pragma unroll
            for (int nt = 0; nt < 4; nt++) {
                int n = wn * 32 + nt * 8 + qr;
                bh[nt][0] = *(const uint32_t*)&sBh[n * PADK + kb + qc];
                bh[nt][1] = *(const uint32_t*)&sBh[n * PADK + kb + qc + 8];
                bl[nt][0] = *(const uint32_t*)&sBl[n * PADK + kb + qc];
                bl[nt][1] = *(const uint32_t*)&sBl[n * PADK + kb + qc + 8];
            }
            // 3 passes: hh, hl, lh
            #pragma unroll
            for (int mt = 0; mt < 2; mt++)
                #pragma unroll
                for (int nt = 0; nt < 4; nt++) {
                    mma_bf16(acc[mt][nt], ah[mt][0], ah[mt][1], ah[mt][2], ah[mt][3],
                             bh[nt][0], bh[nt][1]);
                    mma_bf16(acc[mt][nt], ah[mt][0], ah[mt][1], ah[mt][2], ah[mt][3],
                             bl[nt][0], bl[nt][1]);
                    mma_bf16(acc[mt][nt], al[mt][0], al[mt][1], al[mt][2], al[mt][3],
                             bh[nt][0], bh[nt][1]);
                }
        }
        __syncthreads();
    }

    // ---- epilogue: c0,c1 -> (row, col..col+1); c2,c3 -> (row+8, ...) ----
    #pragma unroll
    for (int mt = 0; mt < 2; mt++) {
        #pragma unroll
        for (int nt = 0; nt < 4; nt++) {
            int r0 = bm + wm * 32 + mt * 16 + qr;
            int c0 = bn + wn * 32 + nt * 8 + qc;
            *(float2*)(C + (size_t)r0 * NT + c0) =
                make_float2(acc[mt][nt][0], acc[mt][nt][1]);
            *(float2*)(C + (size_t)(r0 + 8) * NT + c0) =
                make_float2(acc[mt][nt][2], acc[mt][nt][3]);
        }
    }
}

// ---------------- edge scatter: agg[dst] += h[src] * dinv[src]*dinv[dst] ----
template <int F>
__global__ void edge_agg_kernel(const int* __restrict__ src_arr,
                                const int* __restrict__ dst_arr,
                                const float* __restrict__ dinv,
                                const float* __restrict__ h,
                                float* __restrict__ agg)
{
    int e    = blockIdx.x * (blockDim.x >> 5) + (threadIdx.x >> 5);
    int lane = threadIdx.x & 31;
    if (e >= N_EDGES) return;

    int s = src_arr[e];
    int d = dst_arr[e];
    float nrm = dinv[s] * dinv[d];

    const float4* hr = (const float4*)(h + (size_t)s * F);
    float* ar = agg + (size_t)d * F;

    #pragma unroll
    for (int c = lane; c < F / 4; c += 32) {
        float4 v = __ldg(hr + c);
        v.x *= nrm; v.y *= nrm; v.z *= nrm; v.w *= nrm;
        red_add_v4(ar + c * 4, v);
    }
}

// ------ finalize layer1: a2 = split(ELU(agg + h/deg + b)) -------------------
__global__ void finalize1_kernel(const float* __restrict__ h1,
                                 const float* __restrict__ agg,
                                 const float* __restrict__ b1,
                                 const float* __restrict__ dinv,
                                 __nv_bfloat16* __restrict__ a2hi,
                                 __nv_bfloat16* __restrict__ a2lo)
{
    size_t idx = (size_t)blockIdx.x * blockDim.x + threadIdx.x;   // float4 units
    size_t total = (size_t)N_NODES * HID / 4;
    if (idx >= total) return;
    int row = (int)(idx * 4 / HID);
    int col = (int)(idx * 4 % HID);

    float id = dinv[row];
    float sl = id * id;

    float4 a = ((const float4*)agg)[idx];
    float4 h = ((const float4*)h1)[idx];
    float4 b = *(const float4*)(b1 + col);

    float v[4] = { a.x + h.x * sl + b.x, a.y + h.y * sl + b.y,
                   a.z + h.z * sl + b.z, a.w + h.w * sl + b.w };
    __nv_bfloat16 hi[4], lo[4];
    #pragma unroll
    for (int i = 0; i < 4; i++) {
        float e = v[i] > 0.0f ? v[i] : expm1f(v[i]);
        hi[i] = __float2bfloat16(e);
        lo[i] = __float2bfloat16(e - __bfloat162float(hi[i]));
    }
    *(uint2*)(a2hi + idx * 4) = *(uint2*)hi;
    *(uint2*)(a2lo + idx * 4) = *(uint2*)lo;
}

// ---------------- finalize layer2 + mean-pool accumulation ------------------
__global__ void fin2_pool_kernel(const float* __restrict__ h2,
                                 const float* __restrict__ agg2,
                                 const float* __restrict__ b2,
                                 const float* __restrict__ dinv,
                                 const int* __restrict__ batch,
                                 float* __restrict__ sums,
                                 int* __restrict__ counts)
{
    int node = blockIdx.x * (blockDim.x >> 5) + (threadIdx.x >> 5);
    int lane = threadIdx.x & 31;
    if (node >= N_NODES) return;

    float id = dinv[node];
    float sl = id * id;
    int g = batch[node];

    float4 a = ((const float4*)(agg2 + (size_t)node * OUT_CH))[lane];
    float4 h = ((const float4*)(h2   + (size_t)node * OUT_CH))[lane];
    float4 b = ((const float4*)b2)[lane];

    float4 v = make_float4(a.x + h.x * sl + b.x, a.y + h.y * sl + b.y,
                           a.z + h.z * sl + b.z, a.w + h.w * sl + b.w);
    red_add_v4(sums + g * OUT_CH + lane * 4, v);
    if (lane == 0) atomicAdd(&counts[g], 1);
}

__global__ void pool_final_kernel(const float* __restrict__ sums,
                                  const int* __restrict__ counts,
                                  float* __restrict__ out)
{
    int c = blockIdx.x * blockDim.x + threadIdx.x;
    if (c < N_GRAPHS * OUT_CH) {
        int g = c / OUT_CH;
        float cnt = fmaxf((float)counts[g], 1.0f);
        out[c] = sums[c] / cnt;
    }
}

__global__ void zero_out_kernel(float* out, int n) {
    int i = blockIdx.x * blockDim.x + threadIdx.x;
    if (i < n) out[i] = 0.0f;
}

// ---------------- launch -----------------------------------------------------
extern "C" void kernel_launch(void* const* d_in, const int* in_sizes, int n_in,
                              void* d_out, int out_size)
{
    const float* x   = nullptr;
    const float* W1  = nullptr;
    const float* b1  = nullptr;
    const float* W2  = nullptr;
    const float* b2  = nullptr;
    const void*  ei  = nullptr;
    const void*  bat = nullptr;

    for (int i = 0; i < n_in; i++) {
        switch (in_sizes[i]) {
            case 12800000: x   = (const float*)d_in[i]; break;
            case 65536:    W1  = (const float*)d_in[i]; break;
            case 256:      b1  = (const float*)d_in[i]; break;
            case 32768:    W2  = (const float*)d_in[i]; break;
            case 128:      b2  = (const float*)d_in[i]; break;
            case 1600000:  ei  = d_in[i];               break;
            case 50000:    bat = d_in[i];               break;
            default: break;
        }
    }
    float* out = (float*)d_out;

    if (!x || !W1 || !b1 || !W2 || !b2 || !ei || !bat) {
        zero_out_kernel<<<(out_size + 255) / 256, 256>>>(out, out_size);
        return;
    }

    void* p;
    cudaGetSymbolAddress(&p, g_deg);     float* deg    = (float*)p;
    cudaGetSymbolAddress(&p, g_dinv);    float* dinv   = (float*)p;
    cudaGetSymbolAddress(&p, g_h1);      float* h1     = (float*)p;
    cudaGetSymbolAddress(&p, g_buf1);    float* buf1   = (float*)p;
    cudaGetSymbolAddress(&p, g_h2);      float* h2     = (float*)p;
    cudaGetSymbolAddress(&p, g_agg2);    float* agg2   = (float*)p;
    cudaGetSymbolAddress(&p, g_sums);    float* sums   = (float*)p;
    cudaGetSymbolAddress(&p, g_counts);  int*   counts = (int*)p;
    cudaGetSymbolAddress(&p, g_src);     int*   src    = (int*)p;
    cudaGetSymbolAddress(&p, g_dst);     int*   dst    = (int*)p;
    cudaGetSymbolAddress(&p, g_batch);   int*   batch  = (int*)p;
    cudaGetSymbolAddress(&p, g_odd_ei);  int*   oddei  = (int*)p;
    cudaGetSymbolAddress(&p, g_odd_bat); int*   oddbat = (int*)p;
    cudaGetSymbolAddress(&p, g_x_hi);    __nv_bfloat16* xhi  = (__nv_bfloat16*)p;
    cudaGetSymbolAddress(&p, g_x_lo);    __nv_bfloat16* xlo  = (__nv_bfloat16*)p;
    cudaGetSymbolAddress(&p, g_a2_hi);   __nv_bfloat16* a2hi = (__nv_bfloat16*)p;
    cudaGetSymbolAddress(&p, g_a2_lo);   __nv_bfloat16* a2lo = (__nv_bfloat16*)p;
    cudaGetSymbolAddress(&p, g_w1t_hi);  __nv_bfloat16* w1hi = (__nv_bfloat16*)p;
    cudaGetSymbolAddress(&p, g_w1t_lo);  __nv_bfloat16* w1lo = (__nv_bfloat16*)p;
    cudaGetSymbolAddress(&p, g_w2t_hi);  __nv_bfloat16* w2hi = (__nv_bfloat16*)p;
    cudaGetSymbolAddress(&p, g_w2t_lo);  __nv_bfloat16* w2lo = (__nv_bfloat16*)p;

    cudaMemsetAsync(deg,    0, N_NODES * sizeof(float));
    cudaMemsetAsync(buf1,   0, (size_t)N_NODES * HID * sizeof(float));
    cudaMemsetAsync(agg2,   0, (size_t)N_NODES * OUT_CH * sizeof(float));
    cudaMemsetAsync(sums,   0, N_GRAPHS * OUT_CH * sizeof(float));
    cudaMemsetAsync(counts, 0, N_GRAPHS * sizeof(int));
    cudaMemsetAsync(oddei,  0, sizeof(int));
    cudaMemsetAsync(oddbat, 0, sizeof(int));

    // dtype detection + index conversion
    detect_kernel<<<(1600000 / 2 + 255) / 256, 256>>>((const int*)ei, 1600000, oddei);
    detect_kernel<<<(50000 / 2 + 255) / 256, 256>>>((const int*)bat, 50000, oddbat);
    conv_ei_kernel<<<(N_EDGES + 255) / 256, 256>>>(ei, src, dst, oddei);
    conv_bat_kernel<<<(N_NODES + 255) / 256, 256>>>(bat, batch, oddbat);

    deg_kernel<<<(N_EDGES + 255) / 256, 256>>>(dst, deg);
    dinv_kernel<<<(N_NODES + 255) / 256, 256>>>(deg, dinv);

    // bf16 splits of operands
    {
        size_t n = (size_t)N_NODES * IN_CH;
        split_x_kernel<<<(unsigned)((n + 255) / 256), 256>>>(x, xhi, xlo);
    }
    split_w_kernel<<<(HID * IN_CH + 255) / 256, 256>>>(W1, IN_CH, HID, w1hi, w1lo);
    split_w_kernel<<<(OUT_CH * HID + 255) / 256, 256>>>(W2, HID, OUT_CH, w2hi, w2lo);

    // h1 = x @ W1  (HMMA, NT=256)
    mma_gemm_kernel<HID><<<dim3(HID / 64, N_PAD / 128), 256>>>(
        xhi, xlo, w1hi, w1lo, h1);

    // scatter layer 1
    edge_agg_kernel<HID><<<(N_EDGES + 7) / 8, 256>>>(src, dst, dinv, h1, buf1);

    // a2 = split(ELU(agg + h/deg + b1))
    {
        size_t total4 = (size_t)N_NODES * HID / 4;
        finalize1_kernel<<<(unsigned)((total4 + 255) / 256), 256>>>(
            h1, buf1, b1, dinv, a2hi, a2lo);
    }

    // h2 = a2 @ W2  (HMMA, NT=128)
    mma_gemm_kernel<OUT_CH><<<dim3(OUT_CH / 64, N_PAD / 128), 256>>>(
        a2hi, a2lo, w2hi, w2lo, h2);

    // scatter layer 2
    edge_agg_kernel<OUT_CH><<<(N_EDGES + 7) / 8, 256>>>(src, dst, dinv, h2, agg2);

    // finalize layer 2 + pool accumulation
    fin2_pool_kernel<<<(N_NODES + 7) / 8, 256>>>(h2, agg2, b2, dinv, batch, sums, counts);

    pool_final_kernel<<<(N_GRAPHS * OUT_CH + 255) / 256, 256>>>(sums, counts, out);
}

// round 6
// speedup vs baseline: 1.9583x; 1.6579x over previous
#include <cuda_runtime.h>
#include <cuda_bf16.h>
#include <cstdint>

#define N_NODES 50000
#define N_PAD   50048      // multiple of 128 for MMA tiles
#define N_EDGES 800000
#define IN_CH 256
#define HID 256
#define OUT_CH 128
#define N_GRAPHS 64
#define SCAN_BLK 512
#define SCAN_NB  ((N_NODES + SCAN_BLK - 1) / SCAN_BLK)   // 98

// ---------------- scratch (device globals; no cudaMalloc allowed) ----------
__device__ float g_dinv[N_NODES];
__device__ int   g_degi[N_NODES];
__device__ int   g_offs[N_NODES];
__device__ int   g_cursor[N_NODES];
__device__ int   g_partials[SCAN_NB];
__device__ int   g_ssrc[N_EDGES];
__device__ float g_h1[(size_t)N_PAD * HID];
__device__ float g_h2[(size_t)N_PAD * OUT_CH];
__device__ float g_sums[N_GRAPHS * OUT_CH];
__device__ int   g_counts[N_GRAPHS];
__device__ int   g_src[N_EDGES];
__device__ int   g_dst[N_EDGES];
__device__ int   g_batch[N_NODES];
__device__ int   g_odd_ei;
__device__ int   g_odd_bat;
// bf16 split operands. Pad rows (>= N_NODES) stay zero: zero-initialized
// device globals, never written.
__device__ __nv_bfloat16 g_a2_hi[(size_t)N_PAD * HID];
__device__ __nv_bfloat16 g_a2_lo[(size_t)N_PAD * HID];
__device__ __nv_bfloat16 g_w1t_hi[HID * IN_CH];     // [n][k] = W1[k][n]
__device__ __nv_bfloat16 g_w1t_lo[HID * IN_CH];
__device__ __nv_bfloat16 g_w2t_hi[OUT_CH * HID];
__device__ __nv_bfloat16 g_w2t_lo[OUT_CH * HID];

// ---------------- helpers ---------------------------------------------------
__device__ __forceinline__ void red_add_v4(float* addr, float4 v) {
    asm volatile("red.global.add.v4.f32 [%0], {%1,%2,%3,%4};"
                 :: "l"(addr), "f"(v.x), "f"(v.y), "f"(v.z), "f"(v.w) : "memory");
}
__device__ __forceinline__ void mma_bf16(float* c, uint32_t a0, uint32_t a1,
                                         uint32_t a2, uint32_t a3,
                                         uint32_t b0, uint32_t b1) {
    asm volatile("mma.sync.aligned.m16n8k16.row.col.f32.bf16.bf16.f32 "
                 "{%0,%1,%2,%3}, {%4,%5,%6,%7}, {%8,%9}, {%0,%1,%2,%3};"
                 : "+f"(c[0]), "+f"(c[1]), "+f"(c[2]), "+f"(c[3])
                 : "r"(a0), "r"(a1), "r"(a2), "r"(a3), "r"(b0), "r"(b1));
}
// split two floats into packed bf16 hi / lo-residual words
__device__ __forceinline__ void split2(float a, float b, uint32_t& hi, uint32_t& lo) {
    __nv_bfloat16 ha = __float2bfloat16(a), hb = __float2bfloat16(b);
    __nv_bfloat16 la = __float2bfloat16(a - __bfloat162float(ha));
    __nv_bfloat16 lb = __float2bfloat16(b - __bfloat162float(hb));
    hi = ((uint32_t)__bfloat16_as_ushort(hb) << 16) | __bfloat16_as_ushort(ha);
    lo = ((uint32_t)__bfloat16_as_ushort(lb) << 16) | __bfloat16_as_ushort(la);
}

// ---------------- dtype detection / conversion ------------------------------
__global__ void detect_kernel(const int* __restrict__ buf32, int nelem32, int* cnt) {
    int i = blockIdx.x * blockDim.x + threadIdx.x;
    int local = 0;
    if (2 * i + 1 < nelem32 && buf32[2 * i + 1] != 0) local = 1;
    unsigned m = __ballot_sync(0xFFFFFFFFu, local);
    if ((threadIdx.x & 31) == 0 && m) atomicAdd(cnt, __popc(m));
}
__global__ void conv_ei_kernel(const void* __restrict__ ei, int* __restrict__ src,
                               int* __restrict__ dst, const int* __restrict__ cnt) {
    int e = blockIdx.x * blockDim.x + threadIdx.x;
    if (e >= N_EDGES) return;
    int s, d;
    if (*cnt < 100) { const long long* p = (const long long*)ei; s = (int)p[e]; d = (int)p[N_EDGES + e]; }
    else            { const int* p = (const int*)ei;             s = p[e];      d = p[N_EDGES + e]; }
    src[e] = min(max(s, 0), N_NODES - 1);
    dst[e] = min(max(d, 0), N_NODES - 1);
}
__global__ void conv_bat_kernel(const void* __restrict__ bat, int* __restrict__ out,
                                const int* __restrict__ cnt) {
    int i = blockIdx.x * blockDim.x + threadIdx.x;
    if (i >= N_NODES) return;
    int g;
    if (*cnt < 100) g = (int)((const long long*)bat)[i];
    else            g = ((const int*)bat)[i];
    out[i] = min(max(g, 0), N_GRAPHS - 1);
}

// ---------------- weight splits ----------------------------------------------
__global__ void split_w_kernel(const float* __restrict__ W, int K, int N,
                               __nv_bfloat16* __restrict__ hi,
                               __nv_bfloat16* __restrict__ lo) {
    int i = blockIdx.x * blockDim.x + threadIdx.x;   // over N*K, transposed out
    if (i >= N * K) return;
    int n = i / K, k = i % K;
    float v = W[(size_t)k * N + n];
    __nv_bfloat16 h = __float2bfloat16(v);
    hi[(size_t)n * K + k] = h;
    lo[(size_t)n * K + k] = __float2bfloat16(v - __bfloat162float(h));
}

// ---------------- CSR build ---------------------------------------------------
__global__ void hist_kernel(const int* __restrict__ dst, int* __restrict__ degi) {
    int e = blockIdx.x * blockDim.x + threadIdx.x;
    if (e < N_EDGES) atomicAdd(&degi[dst[e]], 1);
}
__global__ void dinv_kernel(const int* __restrict__ degi, float* __restrict__ dinv) {
    int i = blockIdx.x * blockDim.x + threadIdx.x;
    if (i < N_NODES) dinv[i] = rsqrtf((float)degi[i] + 1.0f);
}
__global__ __launch_bounds__(SCAN_BLK) void scan1_kernel(
    const int* __restrict__ degi, int* __restrict__ offs, int* __restrict__ partials) {
    __shared__ int sm[SCAN_BLK];
    int i = blockIdx.x * SCAN_BLK + threadIdx.x;
    int v = (i < N_NODES) ? degi[i] : 0;
    sm[threadIdx.x] = v;
    __syncthreads();
    for (int d = 1; d < SCAN_BLK; d <<= 1) {
        int t = (threadIdx.x >= d) ? sm[threadIdx.x - d] : 0;
        __syncthreads();
        sm[threadIdx.x] += t;
        __syncthreads();
    }
    if (i < N_NODES) offs[i] = sm[threadIdx.x] - v;       // exclusive
    if (threadIdx.x == SCAN_BLK - 1) partials[blockIdx.x] = sm[SCAN_BLK - 1];
}
__global__ void scan2_kernel(int* partials) {
    if (threadIdx.x == 0 && blockIdx.x == 0) {
        int run = 0;
        for (int b = 0; b < SCAN_NB; b++) { int v = partials[b]; partials[b] = run; run += v; }
    }
}
__global__ void scan3_kernel(int* __restrict__ offs, int* __restrict__ cursor,
                             const int* __restrict__ partials) {
    int i = blockIdx.x * blockDim.x + threadIdx.x;
    if (i < N_NODES) {
        int o = offs[i] + partials[i / SCAN_BLK];
        offs[i] = o;
        cursor[i] = o;
    }
}
__global__ void scatter_build_kernel(const int* __restrict__ src, const int* __restrict__ dst,
                                     int* __restrict__ cursor, int* __restrict__ ssrc) {
    int e = blockIdx.x * blockDim.x + threadIdx.x;
    if (e >= N_EDGES) return;
    int pos = atomicAdd(&cursor[dst[e]], 1);
    ssrc[pos] = src[e];
}

// ---------------- HMMA GEMM: C[Mpad,NT] = A[Mpad,256] @ Wt[NT,256]^T --------
// AFP32: A is fp32, split into (hi,lo) bf16 in SMEM. Else A pre-split bf16 pair.
// 3-pass: hh + hl + lh, fp32 accumulate. CTA 128x64, BK=32, 8 warps (4Mx2N).
#define PADK 40
template <int NT, bool AFP32>
__global__ __launch_bounds__(256) void mma_gemm_kernel(
    const void* __restrict__ A_, const void* __restrict__ Alo_,
    const __nv_bfloat16* __restrict__ Bhi, const __nv_bfloat16* __restrict__ Blo,
    float* __restrict__ C)
{
    constexpr int K = 256;
    __shared__ __align__(16) __nv_bfloat16 sAh[128 * PADK];
    __shared__ __align__(16) __nv_bfloat16 sAl[128 * PADK];
    __shared__ __align__(16) __nv_bfloat16 sBh[64 * PADK];
    __shared__ __align__(16) __nv_bfloat16 sBl[64 * PADK];

    const int tid  = threadIdx.x;
    const int lane = tid & 31;
    const int wid  = tid >> 5;
    const int wm   = wid & 3;
    const int wn   = wid >> 2;
    const int bm   = blockIdx.y * 128;
    const int bn   = blockIdx.x * 64;

    float acc[2][4][4];
    #pragma unroll
    for (int mt = 0; mt < 2; mt++)
        #pragma unroll
        for (int nt = 0; nt < 4; nt++)
            #pragma unroll
            for (int j = 0; j < 4; j++) acc[mt][nt][j] = 0.0f;

    const int qr = lane >> 2;
    const int qc = (lane & 3) * 2;

    for (int kc = 0; kc < K; kc += 32) {
        if constexpr (AFP32) {
            const float* A = (const float*)A_;
            #pragma unroll
            for (int t = tid; t < 512; t += 256) {
                int r = t >> 2, i = t & 3;
                float4 f0 = make_float4(0.f, 0.f, 0.f, 0.f), f1 = f0;
                if (bm + r < N_NODES) {
                    size_t gi = (size_t)(bm + r) * K + kc + i * 8;
                    f0 = *(const float4*)(A + gi);
                    f1 = *(const float4*)(A + gi + 4);
                }
                uint32_t h01, h23, h45, h67, l01, l23, l45, l67;
                split2(f0.x, f0.y, h01, l01);
                split2(f0.z, f0.w, h23, l23);
                split2(f1.x, f1.y, h45, l45);
                split2(f1.z, f1.w, h67, l67);
                *(uint4*)&sAh[r * PADK + i * 8] = make_uint4(h01, h23, h45, h67);
                *(uint4*)&sAl[r * PADK + i * 8] = make_uint4(l01, l23, l45, l67);
            }
        } else {
            const __nv_bfloat16* Ahi = (const __nv_bfloat16*)A_;
            const __nv_bfloat16* Alo = (const __nv_bfloat16*)Alo_;
            #pragma unroll
            for (int t = tid; t < 512; t += 256) {
                int r = t >> 2, i = t & 3;
                size_t gi = (size_t)(bm + r) * K + kc + i * 8;
                *(uint4*)&sAh[r * PADK + i * 8] = *(const uint4*)(Ahi + gi);
                *(uint4*)&sAl[r * PADK + i * 8] = *(const uint4*)(Alo + gi);
            }
        }
        {
            int t = tid;
            int r = t >> 2, i = t & 3;
            size_t gi = (size_t)(bn + r) * K + kc + i * 8;
            *(uint4*)&sBh[r * PADK + i * 8] = *(const uint4*)(Bhi + gi);
            *(uint4*)&sBl[r * PADK + i * 8] = *(const uint4*)(Blo + gi);
        }
        __syncthreads();

        #pragma unroll
        for (int ks = 0; ks < 2; ks++) {
            const int kb = ks * 16;
            uint32_t ah[2][4], al[2][4];
            #pragma unroll
            for (int mt = 0; mt < 2; mt++) {
                int r0 = wm * 32 + mt * 16 + qr;
                #pragma unroll
                for (int h = 0; h < 2; h++) {
                    int r = r0 + h * 8;
                    ah[mt][h]     = *(const uint32_t*)&sAh[r * PADK + kb + qc];
                    ah[mt][h + 2] = *(const uint32_t*)&sAh[r * PADK + kb + qc + 8];
                    al[mt][h]     = *(const uint32_t*)&sAl[r * PADK + kb + qc];
                    al[mt][h + 2] = *(const uint32_t*)&sAl[r * PADK + kb + qc + 8];
                }
            }
            uint32_t bh[4][2], bl[4][2];
            #pragma unroll
            for (int nt = 0; nt < 4; nt++) {
                int n = wn * 32 + nt * 8 + qr;
                bh[nt][0] = *(const uint32_t*)&sBh[n * PADK + kb + qc];
                bh[nt][1] = *(const uint32_t*)&sBh[n * PADK + kb + qc + 8];
                bl[nt][0] = *(const uint32_t*)&sBl[n * PADK + kb + qc];
                bl[nt][1] = *(const uint32_t*)&sBl[n * PADK + kb + qc + 8];
            }
            #pragma unroll
            for (int mt = 0; mt < 2; mt++)
                #pragma unroll
                for (int nt = 0; nt < 4; nt++) {
                    mma_bf16(acc[mt][nt], ah[mt][0], ah[mt][1], ah[mt][2], ah[mt][3],
                             bh[nt][0], bh[nt][1]);
                    mma_bf16(acc[mt][nt], ah[mt][0], ah[mt][1], ah[mt][2], ah[mt][3],
                             bl[nt][0], bl[nt][1]);
                    mma_bf16(acc[mt][nt], al[mt][0], al[mt][1], al[mt][2], al[mt][3],
                             bh[nt][0], bh[nt][1]);
                }
        }
        __syncthreads();
    }

    #pragma unroll
    for (int mt = 0; mt < 2; mt++) {
        #pragma unroll
        for (int nt = 0; nt < 4; nt++) {
            int r0 = bm + wm * 32 + mt * 16 + qr;
            int c0 = bn + wn * 32 + nt * 8 + qc;
            *(float2*)(C + (size_t)r0 * NT + c0) =
                make_float2(acc[mt][nt][0], acc[mt][nt][1]);
            *(float2*)(C + (size_t)(r0 + 8) * NT + c0) =
                make_float2(acc[mt][nt][2], acc[mt][nt][3]);
        }
    }
}

// ---------------- CSR gather aggregation -------------------------------------
// MODE 0 (layer 1): out = split(ELU(agg + h/deg + b))  -> a2hi/a2lo
// MODE 1 (layer 2): red-add (agg + h/deg + b) into sums[batch[node]]
template <int F, int MODE>
__global__ __launch_bounds__(128) void gather_kernel(
    const int* __restrict__ offs, const int* __restrict__ degi,
    const int* __restrict__ ssrc, const float* __restrict__ dinv,
    const float* __restrict__ h, const float* __restrict__ bias,
    __nv_bfloat16* __restrict__ ohi, __nv_bfloat16* __restrict__ olo,
    const int* __restrict__ batch, float* __restrict__ sums,
    int* __restrict__ counts)
{
    constexpr int NV = F / 128;                   // float4s per lane
    int node = blockIdx.x * 4 + (threadIdx.x >> 5);
    int lane = threadIdx.x & 31;
    if (node >= N_NODES) return;

    int start = offs[node];
    int dg    = degi[node];
    float dn  = dinv[node];

    float4 acc[NV];
    #pragma unroll
    for (int v = 0; v < NV; v++) acc[v] = make_float4(0.f, 0.f, 0.f, 0.f);

    int j = 0;
    for (; j + 2 <= dg; j += 2) {
        int s0 = __ldg(&ssrc[start + j]);
        int s1 = __ldg(&ssrc[start + j + 1]);
        float w0 = __ldg(&dinv[s0]) * dn;
        float w1 = __ldg(&dinv[s1]) * dn;
        #pragma unroll
        for (int v = 0; v < NV; v++) {
            float4 a = __ldg((const float4*)(h + (size_t)s0 * F + v * 128) + lane);
            float4 b = __ldg((const float4*)(h + (size_t)s1 * F + v * 128) + lane);
            acc[v].x += w0 * a.x + w1 * b.x;
            acc[v].y += w0 * a.y + w1 * b.y;
            acc[v].z += w0 * a.z + w1 * b.z;
            acc[v].w += w0 * a.w + w1 * b.w;
        }
    }
    if (j < dg) {
        int s0 = __ldg(&ssrc[start + j]);
        float w0 = __ldg(&dinv[s0]) * dn;
        #pragma unroll
        for (int v = 0; v < NV; v++) {
            float4 a = __ldg((const float4*)(h + (size_t)s0 * F + v * 128) + lane);
            acc[v].x += w0 * a.x;
            acc[v].y += w0 * a.y;
            acc[v].z += w0 * a.z;
            acc[v].w += w0 * a.w;
        }
    }

    float sl = dn * dn;      // 1/deg (self-loop weight)
    if constexpr (MODE == 0) {
        #pragma unroll
        for (int v = 0; v < NV; v++) {
            int col = v * 128 + lane * 4;
            float4 hv = *(const float4*)(h + (size_t)node * F + col);
            float4 bv = *(const float4*)(bias + col);
            float r0 = acc[v].x + hv.x * sl + bv.x;
            float r1 = acc[v].y + hv.y * sl + bv.y;
            float r2 = acc[v].z + hv.z * sl + bv.z;
            float r3 = acc[v].w + hv.w * sl + bv.w;
            r0 = r0 > 0.f ? r0 : expm1f(r0);
            r1 = r1 > 0.f ? r1 : expm1f(r1);
            r2 = r2 > 0.f ? r2 : expm1f(r2);
            r3 = r3 > 0.f ? r3 : expm1f(r3);
            uint32_t h01, h23, l01, l23;
            split2(r0, r1, h01, l01);
            split2(r2, r3, h23, l23);
            *(uint2*)(ohi + (size_t)node * F + col) = make_uint2(h01, h23);
            *(uint2*)(olo + (size_t)node * F + col) = make_uint2(l01, l23);
        }
    } else {
        int g = batch[node];
        int col = lane * 4;
        float4 hv = *(const float4*)(h + (size_t)node * F + col);
        float4 bv = *(const float4*)(bias + col);
        float4 r = make_float4(acc[0].x + hv.x * sl + bv.x,
                               acc[0].y + hv.y * sl + bv.y,
                               acc[0].z + hv.z * sl + bv.z,
                               acc[0].w + hv.w * sl + bv.w);
        red_add_v4(sums + g * F + col, r);
        if (lane == 0) atomicAdd(&counts[g], 1);
    }
}

__global__ void pool_final_kernel(const float* __restrict__ sums,
                                  const int* __restrict__ counts,
                                  float* __restrict__ out)
{
    int c = blockIdx.x * blockDim.x + threadIdx.x;
    if (c < N_GRAPHS * OUT_CH) {
        int g = c / OUT_CH;
        float cnt = fmaxf((float)counts[g], 1.0f);
        out[c] = sums[c] / cnt;
    }
}

__global__ void zero_out_kernel(float* out, int n) {
    int i = blockIdx.x * blockDim.x + threadIdx.x;
    if (i < n) out[i] = 0.0f;
}

// ---------------- launch -----------------------------------------------------
extern "C" void kernel_launch(void* const* d_in, const int* in_sizes, int n_in,
                              void* d_out, int out_size)
{
    const float* x   = nullptr;
    const float* W1  = nullptr;
    const float* b1  = nullptr;
    const float* W2  = nullptr;
    const float* b2  = nullptr;
    const void*  ei  = nullptr;
    const void*  bat = nullptr;

    for (int i = 0; i < n_in; i++) {
        switch (in_sizes[i]) {
            case 12800000: x   = (const float*)d_in[i]; break;
            case 65536:    W1  = (const float*)d_in[i]; break;
            case 256:      b1  = (const float*)d_in[i]; break;
            case 32768:    W2  = (const float*)d_in[i]; break;
            case 128:      b2  = (const float*)d_in[i]; break;
            case 1600000:  ei  = d_in[i];               break;
            case 50000:    bat = d_in[i];               break;
            default: break;
        }
    }
    float* out = (float*)d_out;

    if (!x || !W1 || !b1 || !W2 || !b2 || !ei || !bat) {
        zero_out_kernel<<<(out_size + 255) / 256, 256>>>(out, out_size);
        return;
    }

    void* p;
    cudaGetSymbolAddress(&p, g_dinv);    float* dinv   = (float*)p;
    cudaGetSymbolAddress(&p, g_degi);    int*   degi   = (int*)p;
    cudaGetSymbolAddress(&p, g_offs);    int*   offs   = (int*)p;
    cudaGetSymbolAddress(&p, g_cursor);  int*   cursor = (int*)p;
    cudaGetSymbolAddress(&p, g_partials);int*   parts  = (int*)p;
    cudaGetSymbolAddress(&p, g_ssrc);    int*   ssrc   = (int*)p;
    cudaGetSymbolAddress(&p, g_h1);      float* h1     = (float*)p;
    cudaGetSymbolAddress(&p, g_h2);      float* h2     = (float*)p;
    cudaGetSymbolAddress(&p, g_sums);    float* sums   = (float*)p;
    cudaGetSymbolAddress(&p, g_counts);  int*   counts = (int*)p;
    cudaGetSymbolAddress(&p, g_src);     int*   src    = (int*)p;
    cudaGetSymbolAddress(&p, g_dst);     int*   dst    = (int*)p;
    cudaGetSymbolAddress(&p, g_batch);   int*   batch  = (int*)p;
    cudaGetSymbolAddress(&p, g_odd_ei);  int*   oddei  = (int*)p;
    cudaGetSymbolAddress(&p, g_odd_bat); int*   oddbat = (int*)p;
    cudaGetSymbolAddress(&p, g_a2_hi);   __nv_bfloat16* a2hi = (__nv_bfloat16*)p;
    cudaGetSymbolAddress(&p, g_a2_lo);   __nv_bfloat16* a2lo = (__nv_bfloat16*)p;
    cudaGetSymbolAddress(&p, g_w1t_hi);  __nv_bfloat16* w1hi = (__nv_bfloat16*)p;
    cudaGetSymbolAddress(&p, g_w1t_lo);  __nv_bfloat16* w1lo = (__nv_bfloat16*)p;
    cudaGetSymbolAddress(&p, g_w2t_hi);  __nv_bfloat16* w2hi = (__nv_bfloat16*)p;
    cudaGetSymbolAddress(&p, g_w2t_lo);  __nv_bfloat16* w2lo = (__nv_bfloat16*)p;

    cudaMemsetAsync(degi,   0, N_NODES * sizeof(int));
    cudaMemsetAsync(sums,   0, N_GRAPHS * OUT_CH * sizeof(float));
    cudaMemsetAsync(counts, 0, N_GRAPHS * sizeof(int));
    cudaMemsetAsync(oddei,  0, sizeof(int));
    cudaMemsetAsync(oddbat, 0, sizeof(int));

    // dtype detection + index conversion
    detect_kernel<<<(1600000 / 2 + 255) / 256, 256>>>((const int*)ei, 1600000, oddei);
    detect_kernel<<<(50000 / 2 + 255) / 256, 256>>>((const int*)bat, 50000, oddbat);
    conv_ei_kernel<<<(N_EDGES + 255) / 256, 256>>>(ei, src, dst, oddei);
    conv_bat_kernel<<<(N_NODES + 255) / 256, 256>>>(bat, batch, oddbat);

    // CSR build
    hist_kernel<<<(N_EDGES + 255) / 256, 256>>>(dst, degi);
    dinv_kernel<<<(N_NODES + 255) / 256, 256>>>(degi, dinv);
    scan1_kernel<<<SCAN_NB, SCAN_BLK>>>(degi, offs, parts);
    scan2_kernel<<<1, 32>>>(parts);
    scan3_kernel<<<(N_NODES + 255) / 256, 256>>>(offs, cursor, parts);
    scatter_build_kernel<<<(N_EDGES + 255) / 256, 256>>>(src, dst, cursor, ssrc);

    // weight splits
    split_w_kernel<<<(HID * IN_CH + 255) / 256, 256>>>(W1, IN_CH, HID, w1hi, w1lo);
    split_w_kernel<<<(OUT_CH * HID + 255) / 256, 256>>>(W2, HID, OUT_CH, w2hi, w2lo);

    // h1 = x @ W1  (HMMA, fp32 A split in-kernel)
    mma_gemm_kernel<HID, true><<<dim3(HID / 64, N_PAD / 128), 256>>>(
        x, nullptr, w1hi, w1lo, h1);

    // layer-1 gather + ELU + bias + split -> a2
    gather_kernel<HID, 0><<<(N_NODES + 3) / 4, 128>>>(
        offs, degi, ssrc, dinv, h1, b1, a2hi, a2lo, nullptr, nullptr, nullptr);

    // h2 = a2 @ W2  (HMMA, pre-split A)
    mma_gemm_kernel<OUT_CH, false><<<dim3(OUT_CH / 64, N_PAD / 128), 256>>>(
        a2hi, a2lo, w2hi, w2lo, h2);

    // layer-2 gather + bias + mean-pool accumulate
    gather_kernel<OUT_CH, 1><<<(N_NODES + 3) / 4, 128>>>(
        offs, degi, ssrc, dinv, h2, b2, nullptr, nullptr, batch, sums, counts);

    pool_final_kernel<<<(N_GRAPHS * OUT_CH + 255) / 256, 256>>>(sums, counts, out);
}

// round 7
// speedup vs baseline: 1.9757x; 1.0089x over previous
#include <cuda_runtime.h>
#include <cuda_bf16.h>
#include <cstdint>

#define N_NODES 50000
#define N_PAD   50048      // multiple of 128 for MMA tiles
#define N_EDGES 800000
#define IN_CH 256
#define HID 256
#define OUT_CH 128
#define N_GRAPHS 64
#define SCAN_BLK 512
#define SCAN_NB  ((N_NODES + SCAN_BLK - 1) / SCAN_BLK)   // 98

// ---------------- scratch (device globals; no cudaMalloc allowed) ----------
__device__ float g_dinv[N_NODES];
__device__ int   g_degi[N_NODES];
__device__ int   g_offs[N_NODES];
__device__ int   g_cursor[N_NODES];
__device__ int   g_partials[SCAN_NB];
__device__ int   g_ssrc[N_EDGES];
__device__ float g_h1[(size_t)N_PAD * HID];
__device__ float g_h2[(size_t)N_PAD * OUT_CH];
__device__ float g_sums[N_GRAPHS * OUT_CH];
__device__ int   g_counts[N_GRAPHS];
__device__ int   g_src[N_EDGES];
__device__ int   g_dst[N_EDGES];
__device__ int   g_batch[N_NODES];
__device__ int   g_odd_ei;
__device__ int   g_odd_bat;
// bf16 split operands. Pad rows (>= N_NODES) stay zero: zero-initialized
// device globals, never written.
__device__ __nv_bfloat16 g_a2_hi[(size_t)N_PAD * HID];
__device__ __nv_bfloat16 g_a2_lo[(size_t)N_PAD * HID];
__device__ __nv_bfloat16 g_w1t_hi[HID * IN_CH];     // [n][k] = W1[k][n]
__device__ __nv_bfloat16 g_w1t_lo[HID * IN_CH];
__device__ __nv_bfloat16 g_w2t_hi[OUT_CH * HID];
__device__ __nv_bfloat16 g_w2t_lo[OUT_CH * HID];

// ---------------- helpers ---------------------------------------------------
__device__ __forceinline__ void red_add_v4(float* addr, float4 v) {
    asm volatile("red.global.add.v4.f32 [%0], {%1,%2,%3,%4};"
                 :: "l"(addr), "f"(v.x), "f"(v.y), "f"(v.z), "f"(v.w) : "memory");
}
__device__ __forceinline__ void mma_bf16(float* c, uint32_t a0, uint32_t a1,
                                         uint32_t a2, uint32_t a3,
                                         uint32_t b0, uint32_t b1) {
    asm volatile("mma.sync.aligned.m16n8k16.row.col.f32.bf16.bf16.f32 "
                 "{%0,%1,%2,%3}, {%4,%5,%6,%7}, {%8,%9}, {%0,%1,%2,%3};"
                 : "+f"(c[0]), "+f"(c[1]), "+f"(c[2]), "+f"(c[3])
                 : "r"(a0), "r"(a1), "r"(a2), "r"(a3), "r"(b0), "r"(b1));
}
__device__ __forceinline__ void split2(float a, float b, uint32_t& hi, uint32_t& lo) {
    __nv_bfloat16 ha = __float2bfloat16(a), hb = __float2bfloat16(b);
    __nv_bfloat16 la = __float2bfloat16(a - __bfloat162float(ha));
    __nv_bfloat16 lb = __float2bfloat16(b - __bfloat162float(hb));
    hi = ((uint32_t)__bfloat16_as_ushort(hb) << 16) | __bfloat16_as_ushort(ha);
    lo = ((uint32_t)__bfloat16_as_ushort(lb) << 16) | __bfloat16_as_ushort(la);
}

// ---------------- dtype detection / conversion ------------------------------
__global__ void detect_kernel(const int* __restrict__ buf32, int nelem32, int* cnt) {
    int i = blockIdx.x * blockDim.x + threadIdx.x;
    int local = 0;
    if (2 * i + 1 < nelem32 && buf32[2 * i + 1] != 0) local = 1;
    unsigned m = __ballot_sync(0xFFFFFFFFu, local);
    if ((threadIdx.x & 31) == 0 && m) atomicAdd(cnt, __popc(m));
}
__global__ void conv_ei_kernel(const void* __restrict__ ei, int* __restrict__ src,
                               int* __restrict__ dst, const int* __restrict__ cnt) {
    int e = blockIdx.x * blockDim.x + threadIdx.x;
    if (e >= N_EDGES) return;
    int s, d;
    if (*cnt < 100) { const long long* p = (const long long*)ei; s = (int)p[e]; d = (int)p[N_EDGES + e]; }
    else            { const int* p = (const int*)ei;             s = p[e];      d = p[N_EDGES + e]; }
    src[e] = min(max(s, 0), N_NODES - 1);
    dst[e] = min(max(d, 0), N_NODES - 1);
}
__global__ void conv_bat_kernel(const void* __restrict__ bat, int* __restrict__ out,
                                const int* __restrict__ cnt) {
    int i = blockIdx.x * blockDim.x + threadIdx.x;
    if (i >= N_NODES) return;
    int g;
    if (*cnt < 100) g = (int)((const long long*)bat)[i];
    else            g = ((const int*)bat)[i];
    out[i] = min(max(g, 0), N_GRAPHS - 1);
}

// ---------------- weight splits ----------------------------------------------
__global__ void split_w_kernel(const float* __restrict__ W, int K, int N,
                               __nv_bfloat16* __restrict__ hi,
                               __nv_bfloat16* __restrict__ lo) {
    int i = blockIdx.x * blockDim.x + threadIdx.x;   // over N*K, transposed out
    if (i >= N * K) return;
    int n = i / K, k = i % K;
    float v = W[(size_t)k * N + n];
    __nv_bfloat16 h = __float2bfloat16(v);
    hi[(size_t)n * K + k] = h;
    lo[(size_t)n * K + k] = __float2bfloat16(v - __bfloat162float(h));
}

// ---------------- CSR build ---------------------------------------------------
__global__ void hist_kernel(const int* __restrict__ dst, int* __restrict__ degi) {
    int e = blockIdx.x * blockDim.x + threadIdx.x;
    if (e < N_EDGES) atomicAdd(&degi[dst[e]], 1);
}
__global__ void dinv_kernel(const int* __restrict__ degi, float* __restrict__ dinv) {
    int i = blockIdx.x * blockDim.x + threadIdx.x;
    if (i < N_NODES) dinv[i] = rsqrtf((float)degi[i] + 1.0f);
}
__global__ __launch_bounds__(SCAN_BLK) void scan1_kernel(
    const int* __restrict__ degi, int* __restrict__ offs, int* __restrict__ partials) {
    __shared__ int sm[SCAN_BLK];
    int i = blockIdx.x * SCAN_BLK + threadIdx.x;
    int v = (i < N_NODES) ? degi[i] : 0;
    sm[threadIdx.x] = v;
    __syncthreads();
    for (int d = 1; d < SCAN_BLK; d <<= 1) {
        int t = (threadIdx.x >= d) ? sm[threadIdx.x - d] : 0;
        __syncthreads();
        sm[threadIdx.x] += t;
        __syncthreads();
    }
    if (i < N_NODES) offs[i] = sm[threadIdx.x] - v;       // exclusive
    if (threadIdx.x == SCAN_BLK - 1) partials[blockIdx.x] = sm[SCAN_BLK - 1];
}
__global__ void scan2_kernel(int* partials) {
    if (threadIdx.x == 0 && blockIdx.x == 0) {
        int run = 0;
        for (int b = 0; b < SCAN_NB; b++) { int v = partials[b]; partials[b] = run; run += v; }
    }
}
__global__ void scan3_kernel(int* __restrict__ offs, int* __restrict__ cursor,
                             const int* __restrict__ partials) {
    int i = blockIdx.x * blockDim.x + threadIdx.x;
    if (i < N_NODES) {
        int o = offs[i] + partials[i / SCAN_BLK];
        offs[i] = o;
        cursor[i] = o;
    }
}
__global__ void scatter_build_kernel(const int* __restrict__ src, const int* __restrict__ dst,
                                     int* __restrict__ cursor, int* __restrict__ ssrc) {
    int e = blockIdx.x * blockDim.x + threadIdx.x;
    if (e >= N_EDGES) return;
    int pos = atomicAdd(&cursor[dst[e]], 1);
    ssrc[pos] = src[e];
}

// ---------------- HMMA GEMM: C[Mpad,NT] = A[Mpad,256] @ Wt[NT,256]^T --------
// CTA tile 128(M) x 128(N), BK=32, register-staged double buffering.
// 8 warps = 4(M) x 2(N); warp tile 32x64 = 2 mt x 8 nt (m16n8k16).
// AFP32: A fp32, split to bf16 hi/lo on the STS path. Else pre-split bf16.
// 3 passes per fragment: hh + hl + lh, fp32 accumulate.
#define PADK 40
template <int NT, bool AFP32>
__global__ __launch_bounds__(256) void mma_gemm_kernel(
    const void* __restrict__ A_, const void* __restrict__ Alo_,
    const __nv_bfloat16* __restrict__ Bhi, const __nv_bfloat16* __restrict__ Blo,
    float* __restrict__ C)
{
    constexpr int K = 256;
    __shared__ __align__(16) __nv_bfloat16 sAh[128 * PADK];
    __shared__ __align__(16) __nv_bfloat16 sAl[128 * PADK];
    __shared__ __align__(16) __nv_bfloat16 sBh[128 * PADK];
    __shared__ __align__(16) __nv_bfloat16 sBl[128 * PADK];

    const int tid  = threadIdx.x;
    const int lane = tid & 31;
    const int wid  = tid >> 5;
    const int wm   = wid & 3;          // 0..3 (M)
    const int wn   = wid >> 2;         // 0..1 (N)
    const int bm   = blockIdx.y * 128;
    const int bn   = blockIdx.x * 128;

    // per-thread load coords: t in {tid, tid+256}, r = t>>2 (row), i = t&3 (16B slot)
    const int r0l = tid >> 2, i0l = (tid & 3) * 8;
    const int r1l = r0l + 64;

    float acc[2][8][4];
    #pragma unroll
    for (int mt = 0; mt < 2; mt++)
        #pragma unroll
        for (int nt = 0; nt < 8; nt++)
            #pragma unroll
            for (int j = 0; j < 4; j++) acc[mt][nt][j] = 0.0f;

    const int qr = lane >> 2;
    const int qc = (lane & 3) * 2;

    // prefetch registers
    float4 pAf[2][2];          // AFP32: 2 iters x 2 float4
    uint4  pAh[2], pAl[2];     // bf16 A: 2 iters
    uint4  pBh[2], pBl[2];

    auto prefetch = [&](int kc) {
        if constexpr (AFP32) {
            const float* A = (const float*)A_;
            #pragma unroll
            for (int it = 0; it < 2; it++) {
                int r = (it == 0) ? r0l : r1l;
                if (bm + r < N_NODES) {
                    size_t gi = (size_t)(bm + r) * K + kc + i0l;
                    pAf[it][0] = *(const float4*)(A + gi);
                    pAf[it][1] = *(const float4*)(A + gi + 4);
                } else {
                    pAf[it][0] = make_float4(0.f, 0.f, 0.f, 0.f);
                    pAf[it][1] = make_float4(0.f, 0.f, 0.f, 0.f);
                }
            }
        } else {
            const __nv_bfloat16* Ahi = (const __nv_bfloat16*)A_;
            const __nv_bfloat16* Alo = (const __nv_bfloat16*)Alo_;
            #pragma unroll
            for (int it = 0; it < 2; it++) {
                int r = (it == 0) ? r0l : r1l;
                size_t gi = (size_t)(bm + r) * K + kc + i0l;
                pAh[it] = *(const uint4*)(Ahi + gi);
                pAl[it] = *(const uint4*)(Alo + gi);
            }
        }
        #pragma unroll
        for (int it = 0; it < 2; it++) {
            int r = (it == 0) ? r0l : r1l;
            size_t gi = (size_t)(bn + r) * K + kc + i0l;
            pBh[it] = *(const uint4*)(Bhi + gi);
            pBl[it] = *(const uint4*)(Blo + gi);
        }
    };

    auto stage = [&]() {
        if constexpr (AFP32) {
            #pragma unroll
            for (int it = 0; it < 2; it++) {
                int r = (it == 0) ? r0l : r1l;
                uint32_t h01, h23, h45, h67, l01, l23, l45, l67;
                split2(pAf[it][0].x, pAf[it][0].y, h01, l01);
                split2(pAf[it][0].z, pAf[it][0].w, h23, l23);
                split2(pAf[it][1].x, pAf[it][1].y, h45, l45);
                split2(pAf[it][1].z, pAf[it][1].w, h67, l67);
                *(uint4*)&sAh[r * PADK + i0l] = make_uint4(h01, h23, h45, h67);
                *(uint4*)&sAl[r * PADK + i0l] = make_uint4(l01, l23, l45, l67);
            }
        } else {
            #pragma unroll
            for (int it = 0; it < 2; it++) {
                int r = (it == 0) ? r0l : r1l;
                *(uint4*)&sAh[r * PADK + i0l] = pAh[it];
                *(uint4*)&sAl[r * PADK + i0l] = pAl[it];
            }
        }
        #pragma unroll
        for (int it = 0; it < 2; it++) {
            int r = (it == 0) ? r0l : r1l;
            *(uint4*)&sBh[r * PADK + i0l] = pBh[it];
            *(uint4*)&sBl[r * PADK + i0l] = pBl[it];
        }
    };

    prefetch(0);
    for (int kc = 0; kc < K; kc += 32) {
        stage();
        __syncthreads();
        if (kc + 32 < K) prefetch(kc + 32);   // LDGs overlap with MMAs below

        #pragma unroll
        for (int ks = 0; ks < 2; ks++) {
            const int kb = ks * 16;
            uint32_t ah[2][4], al[2][4];
            #pragma unroll
            for (int mt = 0; mt < 2; mt++) {
                int rr = wm * 32 + mt * 16 + qr;
                #pragma unroll
                for (int h = 0; h < 2; h++) {
                    int r = rr + h * 8;
                    ah[mt][h]     = *(const uint32_t*)&sAh[r * PADK + kb + qc];
                    ah[mt][h + 2] = *(const uint32_t*)&sAh[r * PADK + kb + qc + 8];
                    al[mt][h]     = *(const uint32_t*)&sAl[r * PADK + kb + qc];
                    al[mt][h + 2] = *(const uint32_t*)&sAl[r * PADK + kb + qc + 8];
                }
            }
            #pragma unroll
            for (int nt = 0; nt < 8; nt++) {
                int n = wn * 64 + nt * 8 + qr;
                uint32_t bh0 = *(const uint32_t*)&sBh[n * PADK + kb + qc];
                uint32_t bh1 = *(const uint32_t*)&sBh[n * PADK + kb + qc + 8];
                uint32_t bl0 = *(const uint32_t*)&sBl[n * PADK + kb + qc];
                uint32_t bl1 = *(const uint32_t*)&sBl[n * PADK + kb + qc + 8];
                #pragma unroll
                for (int mt = 0; mt < 2; mt++) {
                    mma_bf16(acc[mt][nt], ah[mt][0], ah[mt][1], ah[mt][2], ah[mt][3],
                             bh0, bh1);
                    mma_bf16(acc[mt][nt], ah[mt][0], ah[mt][1], ah[mt][2], ah[mt][3],
                             bl0, bl1);
                    mma_bf16(acc[mt][nt], al[mt][0], al[mt][1], al[mt][2], al[mt][3],
                             bh0, bh1);
                }
            }
        }
        __syncthreads();
    }

    #pragma unroll
    for (int mt = 0; mt < 2; mt++) {
        #pragma unroll
        for (int nt = 0; nt < 8; nt++) {
            int r0 = bm + wm * 32 + mt * 16 + qr;
            int c0 = bn + wn * 64 + nt * 8 + qc;
            *(float2*)(C + (size_t)r0 * NT + c0) =
                make_float2(acc[mt][nt][0], acc[mt][nt][1]);
            *(float2*)(C + (size_t)(r0 + 8) * NT + c0) =
                make_float2(acc[mt][nt][2], acc[mt][nt][3]);
        }
    }
}

// ---------------- CSR gather aggregation -------------------------------------
// MODE 0 (layer 1): out = split(ELU(agg + h/deg + b))  -> a2hi/a2lo
// MODE 1 (layer 2): red-add (agg + h/deg + b) into sums[batch[node]]
template <int F, int MODE>
__global__ __launch_bounds__(128) void gather_kernel(
    const int* __restrict__ offs, const int* __restrict__ degi,
    const int* __restrict__ ssrc, const float* __restrict__ dinv,
    const float* __restrict__ h, const float* __restrict__ bias,
    __nv_bfloat16* __restrict__ ohi, __nv_bfloat16* __restrict__ olo,
    const int* __restrict__ batch, float* __restrict__ sums,
    int* __restrict__ counts)
{
    constexpr int NV = F / 128;                   // float4s per lane
    int node = blockIdx.x * 4 + (threadIdx.x >> 5);
    int lane = threadIdx.x & 31;
    if (node >= N_NODES) return;

    int start = offs[node];
    int dg    = degi[node];
    float dn  = dinv[node];

    float4 acc[NV];
    #pragma unroll
    for (int v = 0; v < NV; v++) acc[v] = make_float4(0.f, 0.f, 0.f, 0.f);

    int j = 0;
    for (; j + 2 <= dg; j += 2) {
        int s0 = __ldg(&ssrc[start + j]);
        int s1 = __ldg(&ssrc[start + j + 1]);
        float w0 = __ldg(&dinv[s0]) * dn;
        float w1 = __ldg(&dinv[s1]) * dn;
        #pragma unroll
        for (int v = 0; v < NV; v++) {
            float4 a = __ldg((const float4*)(h + (size_t)s0 * F + v * 128) + lane);
            float4 b = __ldg((const float4*)(h + (size_t)s1 * F + v * 128) + lane);
            acc[v].x += w0 * a.x + w1 * b.x;
            acc[v].y += w0 * a.y + w1 * b.y;
            acc[v].z += w0 * a.z + w1 * b.z;
            acc[v].w += w0 * a.w + w1 * b.w;
        }
    }
    if (j < dg) {
        int s0 = __ldg(&ssrc[start + j]);
        float w0 = __ldg(&dinv[s0]) * dn;
        #pragma unroll
        for (int v = 0; v < NV; v++) {
            float4 a = __ldg((const float4*)(h + (size_t)s0 * F + v * 128) + lane);
            acc[v].x += w0 * a.x;
            acc[v].y += w0 * a.y;
            acc[v].z += w0 * a.z;
            acc[v].w += w0 * a.w;
        }
    }

    float sl = dn * dn;      // 1/deg (self-loop weight)
    if constexpr (MODE == 0) {
        #pragma unroll
        for (int v = 0; v < NV; v++) {
            int col = v * 128 + lane * 4;
            float4 hv = *(const float4*)(h + (size_t)node * F + col);
            float4 bv = *(const float4*)(bias + col);
            float r0 = acc[v].x + hv.x * sl + bv.x;
            float r1 = acc[v].y + hv.y * sl + bv.y;
            float r2 = acc[v].z + hv.z * sl + bv.z;
            float r3 = acc[v].w + hv.w * sl + bv.w;
            r0 = r0 > 0.f ? r0 : expm1f(r0);
            r1 = r1 > 0.f ? r1 : expm1f(r1);
            r2 = r2 > 0.f ? r2 : expm1f(r2);
            r3 = r3 > 0.f ? r3 : expm1f(r3);
            uint32_t h01, h23, l01, l23;
            split2(r0, r1, h01, l01);
            split2(r2, r3, h23, l23);
            *(uint2*)(ohi + (size_t)node * F + col) = make_uint2(h01, h23);
            *(uint2*)(olo + (size_t)node * F + col) = make_uint2(l01, l23);
        }
    } else {
        int g = batch[node];
        int col = lane * 4;
        float4 hv = *(const float4*)(h + (size_t)node * F + col);
        float4 bv = *(const float4*)(bias + col);
        float4 r = make_float4(acc[0].x + hv.x * sl + bv.x,
                               acc[0].y + hv.y * sl + bv.y,
                               acc[0].z + hv.z * sl + bv.z,
                               acc[0].w + hv.w * sl + bv.w);
        red_add_v4(sums + g * F + col, r);
        if (lane == 0) atomicAdd(&counts[g], 1);
    }
}

__global__ void pool_final_kernel(const float* __restrict__ sums,
                                  const int* __restrict__ counts,
                                  float* __restrict__ out)
{
    int c = blockIdx.x * blockDim.x + threadIdx.x;
    if (c < N_GRAPHS * OUT_CH) {
        int g = c / OUT_CH;
        float cnt = fmaxf((float)counts[g], 1.0f);
        out[c] = sums[c] / cnt;
    }
}

__global__ void zero_out_kernel(float* out, int n) {
    int i = blockIdx.x * blockDim.x + threadIdx.x;
    if (i < n) out[i] = 0.0f;
}

// ---------------- launch -----------------------------------------------------
extern "C" void kernel_launch(void* const* d_in, const int* in_sizes, int n_in,
                              void* d_out, int out_size)
{
    const float* x   = nullptr;
    const float* W1  = nullptr;
    const float* b1  = nullptr;
    const float* W2  = nullptr;
    const float* b2  = nullptr;
    const void*  ei  = nullptr;
    const void*  bat = nullptr;

    for (int i = 0; i < n_in; i++) {
        switch (in_sizes[i]) {
            case 12800000: x   = (const float*)d_in[i]; break;
            case 65536:    W1  = (const float*)d_in[i]; break;
            case 256:      b1  = (const float*)d_in[i]; break;
            case 32768:    W2  = (const float*)d_in[i]; break;
            case 128:      b2  = (const float*)d_in[i]; break;
            case 1600000:  ei  = d_in[i];               break;
            case 50000:    bat = d_in[i];               break;
            default: break;
        }
    }
    float* out = (float*)d_out;

    if (!x || !W1 || !b1 || !W2 || !b2 || !ei || !bat) {
        zero_out_kernel<<<(out_size + 255) / 256, 256>>>(out, out_size);
        return;
    }

    void* p;
    cudaGetSymbolAddress(&p, g_dinv);    float* dinv   = (float*)p;
    cudaGetSymbolAddress(&p, g_degi);    int*   degi   = (int*)p;
    cudaGetSymbolAddress(&p, g_offs);    int*   offs   = (int*)p;
    cudaGetSymbolAddress(&p, g_cursor);  int*   cursor = (int*)p;
    cudaGetSymbolAddress(&p, g_partials);int*   parts  = (int*)p;
    cudaGetSymbolAddress(&p, g_ssrc);    int*   ssrc   = (int*)p;
    cudaGetSymbolAddress(&p, g_h1);      float* h1     = (float*)p;
    cudaGetSymbolAddress(&p, g_h2);      float* h2     = (float*)p;
    cudaGetSymbolAddress(&p, g_sums);    float* sums   = (float*)p;
    cudaGetSymbolAddress(&p, g_counts);  int*   counts = (int*)p;
    cudaGetSymbolAddress(&p, g_src);     int*   src    = (int*)p;
    cudaGetSymbolAddress(&p, g_dst);     int*   dst    = (int*)p;
    cudaGetSymbolAddress(&p, g_batch);   int*   batch  = (int*)p;
    cudaGetSymbolAddress(&p, g_odd_ei);  int*   oddei  = (int*)p;
    cudaGetSymbolAddress(&p, g_odd_bat); int*   oddbat = (int*)p;
    cudaGetSymbolAddress(&p, g_a2_hi);   __nv_bfloat16* a2hi = (__nv_bfloat16*)p;
    cudaGetSymbolAddress(&p, g_a2_lo);   __nv_bfloat16* a2lo = (__nv_bfloat16*)p;
    cudaGetSymbolAddress(&p, g_w1t_hi);  __nv_bfloat16* w1hi = (__nv_bfloat16*)p;
    cudaGetSymbolAddress(&p, g_w1t_lo);  __nv_bfloat16* w1lo = (__nv_bfloat16*)p;
    cudaGetSymbolAddress(&p, g_w2t_hi);  __nv_bfloat16* w2hi = (__nv_bfloat16*)p;
    cudaGetSymbolAddress(&p, g_w2t_lo);  __nv_bfloat16* w2lo = (__nv_bfloat16*)p;

    cudaMemsetAsync(degi,   0, N_NODES * sizeof(int));
    cudaMemsetAsync(sums,   0, N_GRAPHS * OUT_CH * sizeof(float));
    cudaMemsetAsync(counts, 0, N_GRAPHS * sizeof(int));
    cudaMemsetAsync(oddei,  0, sizeof(int));
    cudaMemsetAsync(oddbat, 0, sizeof(int));

    // dtype detection + index conversion
    detect_kernel<<<(1600000 / 2 + 255) / 256, 256>>>((const int*)ei, 1600000, oddei);
    detect_kernel<<<(50000 / 2 + 255) / 256, 256>>>((const int*)bat, 50000, oddbat);
    conv_ei_kernel<<<(N_EDGES + 255) / 256, 256>>>(ei, src, dst, oddei);
    conv_bat_kernel<<<(N_NODES + 255) / 256, 256>>>(bat, batch, oddbat);

    // CSR build
    hist_kernel<<<(N_EDGES + 255) / 256, 256>>>(dst, degi);
    dinv_kernel<<<(N_NODES + 255) / 256, 256>>>(degi, dinv);
    scan1_kernel<<<SCAN_NB, SCAN_BLK>>>(degi, offs, parts);
    scan2_kernel<<<1, 32>>>(parts);
    scan3_kernel<<<(N_NODES + 255) / 256, 256>>>(offs, cursor, parts);
    scatter_build_kernel<<<(N_EDGES + 255) / 256, 256>>>(src, dst, cursor, ssrc);

    // weight splits
    split_w_kernel<<<(HID * IN_CH + 255) / 256, 256>>>(W1, IN_CH, HID, w1hi, w1lo);
    split_w_kernel<<<(OUT_CH * HID + 255) / 256, 256>>>(W2, HID, OUT_CH, w2hi, w2lo);

    // h1 = x @ W1  (HMMA, fp32 A split in-kernel, 128x128 tiles)
    mma_gemm_kernel<HID, true><<<dim3(HID / 128, N_PAD / 128), 256>>>(
        x, nullptr, w1hi, w1lo, h1);

    // layer-1 gather + ELU + bias + split -> a2
    gather_kernel<HID, 0><<<(N_NODES + 3) / 4, 128>>>(
        offs, degi, ssrc, dinv, h1, b1, a2hi, a2lo, nullptr, nullptr, nullptr);

    // h2 = a2 @ W2  (HMMA, pre-split A, 128x128 tiles)
    mma_gemm_kernel<OUT_CH, false><<<dim3(OUT_CH / 128, N_PAD / 128), 256>>>(
        a2hi, a2lo, w2hi, w2lo, h2);

    // layer-2 gather + bias + mean-pool accumulate
    gather_kernel<OUT_CH, 1><<<(N_NODES + 3) / 4, 128>>>(
        offs, degi, ssrc, dinv, h2, b2, nullptr, nullptr, batch, sums, counts);

    pool_final_kernel<<<(N_GRAPHS * OUT_CH + 255) / 256, 256>>>(sums, counts, out);
}

// round 8
// speedup vs baseline: 2.5970x; 1.3145x over previous
#include <cuda_runtime.h>
#include <cuda_fp16.h>
#include <cstdint>

#define N_NODES 50000
#define N_PAD   50048      // multiple of 128 for MMA tiles
#define N_EDGES 800000
#define IN_CH 256
#define HID 256
#define OUT_CH 128
#define N_GRAPHS 64
#define SCAN_BLK 512
#define SCAN_NB  ((N_NODES + SCAN_BLK - 1) / SCAN_BLK)   // 98

// ---------------- scratch (device globals; no cudaMalloc allowed) ----------
__device__ float g_dinv[N_NODES];
__device__ int   g_degi[N_NODES];
__device__ int   g_offs[N_NODES];
__device__ int   g_cursor[N_NODES];
__device__ int   g_partials[SCAN_NB];
__device__ int   g_ssrc[N_EDGES];
__device__ float g_h1[(size_t)N_PAD * HID];
__device__ float g_h2[(size_t)N_PAD * OUT_CH];
__device__ float g_sums[N_GRAPHS * OUT_CH];
__device__ int   g_counts[N_GRAPHS];
__device__ int   g_src[N_EDGES];
__device__ int   g_dst[N_EDGES];
__device__ int   g_batch[N_NODES];
__device__ int   g_odd_ei;
__device__ int   g_odd_bat;
// fp16 operands. Pad rows (>= N_NODES) of g_a2 stay zero: zero-initialized
// device globals, never written.
__device__ __half g_a2[(size_t)N_PAD * HID];
__device__ __half g_w1t[HID * IN_CH];     // [n][k] = W1[k][n]
__device__ __half g_w2t[OUT_CH * HID];

// ---------------- helpers ---------------------------------------------------
__device__ __forceinline__ void red_add_v4(float* addr, float4 v) {
    asm volatile("red.global.add.v4.f32 [%0], {%1,%2,%3,%4};"
                 :: "l"(addr), "f"(v.x), "f"(v.y), "f"(v.z), "f"(v.w) : "memory");
}
__device__ __forceinline__ void mma_f16(float* c, uint32_t a0, uint32_t a1,
                                        uint32_t a2, uint32_t a3,
                                        uint32_t b0, uint32_t b1) {
    asm volatile("mma.sync.aligned.m16n8k16.row.col.f32.f16.f16.f32 "
                 "{%0,%1,%2,%3}, {%4,%5,%6,%7}, {%8,%9}, {%0,%1,%2,%3};"
                 : "+f"(c[0]), "+f"(c[1]), "+f"(c[2]), "+f"(c[3])
                 : "r"(a0), "r"(a1), "r"(a2), "r"(a3), "r"(b0), "r"(b1));
}
__device__ __forceinline__ uint32_t pack_h2(float a, float b) {
    __half2 h = __floats2half2_rn(a, b);
    return *reinterpret_cast<uint32_t*>(&h);
}

// ---------------- dtype detection -------------------------------------------
__global__ void detect_kernel(const int* __restrict__ buf32, int nelem32, int* cnt) {
    int i = blockIdx.x * blockDim.x + threadIdx.x;
    int local = 0;
    if (2 * i + 1 < nelem32 && buf32[2 * i + 1] != 0) local = 1;
    unsigned m = __ballot_sync(0xFFFFFFFFu, local);
    if ((threadIdx.x & 31) == 0 && m) atomicAdd(cnt, __popc(m));
}
// fused: edge conversion + degree histogram
__global__ void ei_hist_kernel(const void* __restrict__ ei, int* __restrict__ src,
                               int* __restrict__ dst, const int* __restrict__ cnt,
                               int* __restrict__ degi) {
    int e = blockIdx.x * blockDim.x + threadIdx.x;
    if (e >= N_EDGES) return;
    int s, d;
    if (*cnt < 100) { const long long* p = (const long long*)ei; s = (int)p[e]; d = (int)p[N_EDGES + e]; }
    else            { const int* p = (const int*)ei;             s = p[e];      d = p[N_EDGES + e]; }
    s = min(max(s, 0), N_NODES - 1);
    d = min(max(d, 0), N_NODES - 1);
    src[e] = s;
    dst[e] = d;
    atomicAdd(&degi[d], 1);
}
// fused: batch conversion + dinv
__global__ void bat_dinv_kernel(const void* __restrict__ bat, int* __restrict__ batch,
                                const int* __restrict__ cnt,
                                const int* __restrict__ degi, float* __restrict__ dinv) {
    int i = blockIdx.x * blockDim.x + threadIdx.x;
    if (i >= N_NODES) return;
    int g;
    if (*cnt < 100) g = (int)((const long long*)bat)[i];
    else            g = ((const int*)bat)[i];
    batch[i] = min(max(g, 0), N_GRAPHS - 1);
    dinv[i] = rsqrtf((float)degi[i] + 1.0f);
}

// ---------------- weight transpose + fp16 convert (both weights) -------------
__global__ void conv_w_kernel(const float* __restrict__ W1, const float* __restrict__ W2,
                              __half* __restrict__ w1t, __half* __restrict__ w2t) {
    int i = blockIdx.x * blockDim.x + threadIdx.x;
    if (i < HID * IN_CH) {
        int n = i / IN_CH, k = i % IN_CH;
        w1t[(size_t)n * IN_CH + k] = __float2half_rn(W1[(size_t)k * HID + n]);
    } else {
        int j = i - HID * IN_CH;
        if (j < OUT_CH * HID) {
            int n = j / HID, k = j % HID;
            w2t[(size_t)n * HID + k] = __float2half_rn(W2[(size_t)k * OUT_CH + n]);
        }
    }
}

// ---------------- CSR scan ----------------------------------------------------
__global__ __launch_bounds__(SCAN_BLK) void scan1_kernel(
    const int* __restrict__ degi, int* __restrict__ offs, int* __restrict__ partials) {
    __shared__ int sm[SCAN_BLK];
    int i = blockIdx.x * SCAN_BLK + threadIdx.x;
    int v = (i < N_NODES) ? degi[i] : 0;
    sm[threadIdx.x] = v;
    __syncthreads();
    for (int d = 1; d < SCAN_BLK; d <<= 1) {
        int t = (threadIdx.x >= d) ? sm[threadIdx.x - d] : 0;
        __syncthreads();
        sm[threadIdx.x] += t;
        __syncthreads();
    }
    if (i < N_NODES) offs[i] = sm[threadIdx.x] - v;       // exclusive
    if (threadIdx.x == SCAN_BLK - 1) partials[blockIdx.x] = sm[SCAN_BLK - 1];
}
__global__ void scan2_kernel(int* partials) {
    if (threadIdx.x == 0 && blockIdx.x == 0) {
        int run = 0;
        for (int b = 0; b < SCAN_NB; b++) { int v = partials[b]; partials[b] = run; run += v; }
    }
}
__global__ void scan3_kernel(int* __restrict__ offs, int* __restrict__ cursor,
                             const int* __restrict__ partials) {
    int i = blockIdx.x * blockDim.x + threadIdx.x;
    if (i < N_NODES) {
        int o = offs[i] + partials[i / SCAN_BLK];
        offs[i] = o;
        cursor[i] = o;
    }
}
__global__ void scatter_build_kernel(const int* __restrict__ src, const int* __restrict__ dst,
                                     int* __restrict__ cursor, int* __restrict__ ssrc) {
    int e = blockIdx.x * blockDim.x + threadIdx.x;
    if (e >= N_EDGES) return;
    int pos = atomicAdd(&cursor[dst[e]], 1);
    ssrc[pos] = src[e];
}

// ---------------- HMMA GEMM: C[Mpad,NT] = A[Mpad,256] @ Wt[NT,256]^T --------
// Single-pass fp16, fp32 accumulate. CTA tile 128x128, BK=32, register-staged
// double buffering. 8 warps = 4(M)x2(N); warp tile 32x64 (m16n8k16, 2mt x 8nt).
// AFP32: A fp32, rounded to fp16 on the STS path. Else A pre-converted fp16.
#define PADK 40
template <int NT, bool AFP32>
__global__ __launch_bounds__(256) void mma_gemm_kernel(
    const void* __restrict__ A_,
    const __half* __restrict__ B,
    float* __restrict__ C)
{
    constexpr int K = 256;
    __shared__ __align__(16) __half sA[128 * PADK];
    __shared__ __align__(16) __half sB[128 * PADK];

    const int tid  = threadIdx.x;
    const int lane = tid & 31;
    const int wid  = tid >> 5;
    const int wm   = wid & 3;
    const int wn   = wid >> 2;
    const int bm   = blockIdx.y * 128;
    const int bn   = blockIdx.x * 128;

    const int r0l = tid >> 2, i0l = (tid & 3) * 8;
    const int r1l = r0l + 64;

    float acc[2][8][4];
    #pragma unroll
    for (int mt = 0; mt < 2; mt++)
        #pragma unroll
        for (int nt = 0; nt < 8; nt++)
            #pragma unroll
            for (int j = 0; j < 4; j++) acc[mt][nt][j] = 0.0f;

    const int qr = lane >> 2;
    const int qc = (lane & 3) * 2;

    float4 pAf[2][2];
    uint4  pA[2];
    uint4  pB[2];

    auto prefetch = [&](int kc) {
        if constexpr (AFP32) {
            const float* A = (const float*)A_;
            #pragma unroll
            for (int it = 0; it < 2; it++) {
                int r = (it == 0) ? r0l : r1l;
                if (bm + r < N_NODES) {
                    size_t gi = (size_t)(bm + r) * K + kc + i0l;
                    pAf[it][0] = *(const float4*)(A + gi);
                    pAf[it][1] = *(const float4*)(A + gi + 4);
                } else {
                    pAf[it][0] = make_float4(0.f, 0.f, 0.f, 0.f);
                    pAf[it][1] = make_float4(0.f, 0.f, 0.f, 0.f);
                }
            }
        } else {
            const __half* A = (const __half*)A_;
            #pragma unroll
            for (int it = 0; it < 2; it++) {
                int r = (it == 0) ? r0l : r1l;
                size_t gi = (size_t)(bm + r) * K + kc + i0l;
                pA[it] = *(const uint4*)(A + gi);
            }
        }
        #pragma unroll
        for (int it = 0; it < 2; it++) {
            int r = (it == 0) ? r0l : r1l;
            size_t gi = (size_t)(bn + r) * K + kc + i0l;
            pB[it] = *(const uint4*)(B + gi);
        }
    };

    auto stage = [&]() {
        if constexpr (AFP32) {
            #pragma unroll
            for (int it = 0; it < 2; it++) {
                int r = (it == 0) ? r0l : r1l;
                uint4 v;
                v.x = pack_h2(pAf[it][0].x, pAf[it][0].y);
                v.y = pack_h2(pAf[it][0].z, pAf[it][0].w);
                v.z = pack_h2(pAf[it][1].x, pAf[it][1].y);
                v.w = pack_h2(pAf[it][1].z, pAf[it][1].w);
                *(uint4*)&sA[r * PADK + i0l] = v;
            }
        } else {
            #pragma unroll
            for (int it = 0; it < 2; it++) {
                int r = (it == 0) ? r0l : r1l;
                *(uint4*)&sA[r * PADK + i0l] = pA[it];
            }
        }
        #pragma unroll
        for (int it = 0; it < 2; it++) {
            int r = (it == 0) ? r0l : r1l;
            *(uint4*)&sB[r * PADK + i0l] = pB[it];
        }
    };

    prefetch(0);
    for (int kc = 0; kc < K; kc += 32) {
        stage();
        __syncthreads();
        if (kc + 32 < K) prefetch(kc + 32);   // LDGs overlap with MMAs below

        #pragma unroll
        for (int ks = 0; ks < 2; ks++) {
            const int kb = ks * 16;
            uint32_t ah[2][4];
            #pragma unroll
            for (int mt = 0; mt < 2; mt++) {
                int rr = wm * 32 + mt * 16 + qr;
                #pragma unroll
                for (int h = 0; h < 2; h++) {
                    int r = rr + h * 8;
                    ah[mt][h]     = *(const uint32_t*)&sA[r * PADK + kb + qc];
                    ah[mt][h + 2] = *(const uint32_t*)&sA[r * PADK + kb + qc + 8];
                }
            }
            #pragma unroll
            for (int nt = 0; nt < 8; nt++) {
                int n = wn * 64 + nt * 8 + qr;
                uint32_t b0 = *(const uint32_t*)&sB[n * PADK + kb + qc];
                uint32_t b1 = *(const uint32_t*)&sB[n * PADK + kb + qc + 8];
                #pragma unroll
                for (int mt = 0; mt < 2; mt++)
                    mma_f16(acc[mt][nt], ah[mt][0], ah[mt][1], ah[mt][2], ah[mt][3],
                            b0, b1);
            }
        }
        __syncthreads();
    }

    #pragma unroll
    for (int mt = 0; mt < 2; mt++) {
        #pragma unroll
        for (int nt = 0; nt < 8; nt++) {
            int r0 = bm + wm * 32 + mt * 16 + qr;
            int c0 = bn + wn * 64 + nt * 8 + qc;
            *(float2*)(C + (size_t)r0 * NT + c0) =
                make_float2(acc[mt][nt][0], acc[mt][nt][1]);
            *(float2*)(C + (size_t)(r0 + 8) * NT + c0) =
                make_float2(acc[mt][nt][2], acc[mt][nt][3]);
        }
    }
}

// ---------------- CSR gather aggregation -------------------------------------
// MODE 0 (layer 1): out = fp16(ELU(agg + h/deg + b)) -> a2
// MODE 1 (layer 2): red-add (agg + h/deg + b) into sums[batch[node]]
template <int F, int MODE>
__global__ __launch_bounds__(128) void gather_kernel(
    const int* __restrict__ offs, const int* __restrict__ degi,
    const int* __restrict__ ssrc, const float* __restrict__ dinv,
    const float* __restrict__ h, const float* __restrict__ bias,
    __half* __restrict__ oh,
    const int* __restrict__ batch, float* __restrict__ sums,
    int* __restrict__ counts)
{
    constexpr int NV = F / 128;                   // float4s per lane
    int node = blockIdx.x * 4 + (threadIdx.x >> 5);
    int lane = threadIdx.x & 31;
    if (node >= N_NODES) return;

    int start = offs[node];
    int dg    = degi[node];
    float dn  = dinv[node];

    float4 acc[NV];
    #pragma unroll
    for (int v = 0; v < NV; v++) acc[v] = make_float4(0.f, 0.f, 0.f, 0.f);

    int j = 0;
    for (; j + 2 <= dg; j += 2) {
        int s0 = __ldg(&ssrc[start + j]);
        int s1 = __ldg(&ssrc[start + j + 1]);
        float w0 = __ldg(&dinv[s0]) * dn;
        float w1 = __ldg(&dinv[s1]) * dn;
        #pragma unroll
        for (int v = 0; v < NV; v++) {
            float4 a = __ldg((const float4*)(h + (size_t)s0 * F + v * 128) + lane);
            float4 b = __ldg((const float4*)(h + (size_t)s1 * F + v * 128) + lane);
            acc[v].x += w0 * a.x + w1 * b.x;
            acc[v].y += w0 * a.y + w1 * b.y;
            acc[v].z += w0 * a.z + w1 * b.z;
            acc[v].w += w0 * a.w + w1 * b.w;
        }
    }
    if (j < dg) {
        int s0 = __ldg(&ssrc[start + j]);
        float w0 = __ldg(&dinv[s0]) * dn;
        #pragma unroll
        for (int v = 0; v < NV; v++) {
            float4 a = __ldg((const float4*)(h + (size_t)s0 * F + v * 128) + lane);
            acc[v].x += w0 * a.x;
            acc[v].y += w0 * a.y;
            acc[v].z += w0 * a.z;
            acc[v].w += w0 * a.w;
        }
    }

    float sl = dn * dn;      // 1/deg (self-loop weight)
    if constexpr (MODE == 0) {
        #pragma unroll
        for (int v = 0; v < NV; v++) {
            int col = v * 128 + lane * 4;
            float4 hv = *(const float4*)(h + (size_t)node * F + col);
            float4 bv = *(const float4*)(bias + col);
            float r0 = acc[v].x + hv.x * sl + bv.x;
            float r1 = acc[v].y + hv.y * sl + bv.y;
            float r2 = acc[v].z + hv.z * sl + bv.z;
            float r3 = acc[v].w + hv.w * sl + bv.w;
            r0 = r0 > 0.f ? r0 : expm1f(r0);
            r1 = r1 > 0.f ? r1 : expm1f(r1);
            r2 = r2 > 0.f ? r2 : expm1f(r2);
            r3 = r3 > 0.f ? r3 : expm1f(r3);
            *(uint2*)(oh + (size_t)node * F + col) =
                make_uint2(pack_h2(r0, r1), pack_h2(r2, r3));
        }
    } else {
        int g = batch[node];
        int col = lane * 4;
        float4 hv = *(const float4*)(h + (size_t)node * F + col);
        float4 bv = *(const float4*)(bias + col);
        float4 r = make_float4(acc[0].x + hv.x * sl + bv.x,
                               acc[0].y + hv.y * sl + bv.y,
                               acc[0].z + hv.z * sl + bv.z,
                               acc[0].w + hv.w * sl + bv.w);
        red_add_v4(sums + g * F + col, r);
        if (lane == 0) atomicAdd(&counts[g], 1);
    }
}

__global__ void pool_final_kernel(const float* __restrict__ sums,
                                  const int* __restrict__ counts,
                                  float* __restrict__ out)
{
    int c = blockIdx.x * blockDim.x + threadIdx.x;
    if (c < N_GRAPHS * OUT_CH) {
        int g = c / OUT_CH;
        float cnt = fmaxf((float)counts[g], 1.0f);
        out[c] = sums[c] / cnt;
    }
}

__global__ void zero_out_kernel(float* out, int n) {
    int i = blockIdx.x * blockDim.x + threadIdx.x;
    if (i < n) out[i] = 0.0f;
}

// ---------------- launch -----------------------------------------------------
extern "C" void kernel_launch(void* const* d_in, const int* in_sizes, int n_in,
                              void* d_out, int out_size)
{
    const float* x   = nullptr;
    const float* W1  = nullptr;
    const float* b1  = nullptr;
    const float* W2  = nullptr;
    const float* b2  = nullptr;
    const void*  ei  = nullptr;
    const void*  bat = nullptr;

    for (int i = 0; i < n_in; i++) {
        switch (in_sizes[i]) {
            case 12800000: x   = (const float*)d_in[i]; break;
            case 65536:    W1  = (const float*)d_in[i]; break;
            case 256:      b1  = (const float*)d_in[i]; break;
            case 32768:    W2  = (const float*)d_in[i]; break;
            case 128:      b2  = (const float*)d_in[i]; break;
            case 1600000:  ei  = d_in[i];               break;
            case 50000:    bat = d_in[i];               break;
            default: break;
        }
    }
    float* out = (float*)d_out;

    if (!x || !W1 || !b1 || !W2 || !b2 || !ei || !bat) {
        zero_out_kernel<<<(out_size + 255) / 256, 256>>>(out, out_size);
        return;
    }

    void* p;
    cudaGetSymbolAddress(&p, g_dinv);    float* dinv   = (float*)p;
    cudaGetSymbolAddress(&p, g_degi);    int*   degi   = (int*)p;
    cudaGetSymbolAddress(&p, g_offs);    int*   offs   = (int*)p;
    cudaGetSymbolAddress(&p, g_cursor);  int*   cursor = (int*)p;
    cudaGetSymbolAddress(&p, g_partials);int*   parts  = (int*)p;
    cudaGetSymbolAddress(&p, g_ssrc);    int*   ssrc   = (int*)p;
    cudaGetSymbolAddress(&p, g_h1);      float* h1     = (float*)p;
    cudaGetSymbolAddress(&p, g_h2);      float* h2     = (float*)p;
    cudaGetSymbolAddress(&p, g_sums);    float* sums   = (float*)p;
    cudaGetSymbolAddress(&p, g_counts);  int*   counts = (int*)p;
    cudaGetSymbolAddress(&p, g_src);     int*   src    = (int*)p;
    cudaGetSymbolAddress(&p, g_dst);     int*   dst    = (int*)p;
    cudaGetSymbolAddress(&p, g_batch);   int*   batch  = (int*)p;
    cudaGetSymbolAddress(&p, g_odd_ei);  int*   oddei  = (int*)p;
    cudaGetSymbolAddress(&p, g_odd_bat); int*   oddbat = (int*)p;
    cudaGetSymbolAddress(&p, g_a2);      __half* a2    = (__half*)p;
    cudaGetSymbolAddress(&p, g_w1t);     __half* w1t   = (__half*)p;
    cudaGetSymbolAddress(&p, g_w2t);     __half* w2t   = (__half*)p;

    cudaMemsetAsync(degi,   0, N_NODES * sizeof(int));
    cudaMemsetAsync(sums,   0, N_GRAPHS * OUT_CH * sizeof(float));
    cudaMemsetAsync(counts, 0, N_GRAPHS * sizeof(int));
    cudaMemsetAsync(oddei,  0, sizeof(int));
    cudaMemsetAsync(oddbat, 0, sizeof(int));

    // dtype detection
    detect_kernel<<<(1600000 / 2 + 255) / 256, 256>>>((const int*)ei, 1600000, oddei);
    detect_kernel<<<(50000 / 2 + 255) / 256, 256>>>((const int*)bat, 50000, oddbat);

    // edge conversion + degree histogram (fused)
    ei_hist_kernel<<<(N_EDGES + 255) / 256, 256>>>(ei, src, dst, oddei, degi);
    // batch conversion + dinv (fused)
    bat_dinv_kernel<<<(N_NODES + 255) / 256, 256>>>(bat, batch, oddbat, degi, dinv);

    // CSR offsets
    scan1_kernel<<<SCAN_NB, SCAN_BLK>>>(degi, offs, parts);
    scan2_kernel<<<1, 32>>>(parts);
    scan3_kernel<<<(N_NODES + 255) / 256, 256>>>(offs, cursor, parts);
    scatter_build_kernel<<<(N_EDGES + 255) / 256, 256>>>(src, dst, cursor, ssrc);

    // weight transpose + fp16 (both weights, one kernel)
    conv_w_kernel<<<(HID * IN_CH + OUT_CH * HID + 255) / 256, 256>>>(W1, W2, w1t, w2t);

    // h1 = x @ W1  (fp16 HMMA, fp32 A rounded in-kernel)
    mma_gemm_kernel<HID, true><<<dim3(HID / 128, N_PAD / 128), 256>>>(x, w1t, h1);

    // layer-1 gather + ELU + bias -> fp16 a2
    gather_kernel<HID, 0><<<(N_NODES + 3) / 4, 128>>>(
        offs, degi, ssrc, dinv, h1, b1, a2, nullptr, nullptr, nullptr);

    // h2 = a2 @ W2  (fp16 HMMA)
    mma_gemm_kernel<OUT_CH, false><<<dim3(OUT_CH / 128, N_PAD / 128), 256>>>(a2, w2t, h2);

    // layer-2 gather + bias + mean-pool accumulate
    gather_kernel<OUT_CH, 1><<<(N_NODES + 3) / 4, 128>>>(
        offs, degi, ssrc, dinv, h2, b2, nullptr, batch, sums, counts);

    pool_final_kernel<<<(N_GRAPHS * OUT_CH + 255) / 256, 256>>>(sums, counts, out);
}

// round 9
// speedup vs baseline: 2.8280x; 1.0889x over previous
#include <cuda_runtime.h>
#include <cuda_fp16.h>
#include <cstdint>

#define N_NODES 50000
#define N_PAD   50048      // multiple of 128 for MMA tiles
#define N_EDGES 800000
#define IN_CH 256
#define HID 256
#define OUT_CH 128
#define N_GRAPHS 64
#define SCAN_BLK 512
#define SCAN_NB  ((N_NODES + SCAN_BLK - 1) / SCAN_BLK)   // 98

// ---------------- scratch (device globals; no cudaMalloc allowed) ----------
__device__ float g_dinv[N_NODES];
__device__ int   g_degi[N_NODES];
__device__ int   g_offs[N_NODES];
__device__ int   g_cursor[N_NODES];
__device__ int   g_partials[SCAN_NB];
__device__ int   g_ssrc[N_EDGES];
__device__ __half g_h1[(size_t)N_PAD * HID];
__device__ __half g_h2[(size_t)N_PAD * OUT_CH];
__device__ float g_sums[N_GRAPHS * OUT_CH];
__device__ int   g_counts[N_GRAPHS];
__device__ int   g_src[N_EDGES];
__device__ int   g_dst[N_EDGES];
__device__ int   g_batch[N_NODES];
__device__ int   g_odd_ei;
__device__ int   g_odd_bat;
// fp16 operands. Pad rows (>= N_NODES) of g_a2 stay zero: zero-initialized
// device globals, never written.
__device__ __half g_a2[(size_t)N_PAD * HID];
__device__ __half g_w1t[HID * IN_CH];     // [n][k] = W1[k][n]
__device__ __half g_w2t[OUT_CH * HID];

// ---------------- helpers ---------------------------------------------------
__device__ __forceinline__ void red_add_v4(float* addr, float4 v) {
    asm volatile("red.global.add.v4.f32 [%0], {%1,%2,%3,%4};"
                 :: "l"(addr), "f"(v.x), "f"(v.y), "f"(v.z), "f"(v.w) : "memory");
}
__device__ __forceinline__ void mma_f16(float* c, uint32_t a0, uint32_t a1,
                                        uint32_t a2, uint32_t a3,
                                        uint32_t b0, uint32_t b1) {
    asm volatile("mma.sync.aligned.m16n8k16.row.col.f32.f16.f16.f32 "
                 "{%0,%1,%2,%3}, {%4,%5,%6,%7}, {%8,%9}, {%0,%1,%2,%3};"
                 : "+f"(c[0]), "+f"(c[1]), "+f"(c[2]), "+f"(c[3])
                 : "r"(a0), "r"(a1), "r"(a2), "r"(a3), "r"(b0), "r"(b1));
}
__device__ __forceinline__ uint32_t pack_h2(float a, float b) {
    __half2 h = __floats2half2_rn(a, b);
    return *reinterpret_cast<uint32_t*>(&h);
}

// ---------------- dtype detection -------------------------------------------
__global__ void detect_kernel(const int* __restrict__ buf32, int nelem32, int* cnt) {
    int i = blockIdx.x * blockDim.x + threadIdx.x;
    int local = 0;
    if (2 * i + 1 < nelem32 && buf32[2 * i + 1] != 0) local = 1;
    unsigned m = __ballot_sync(0xFFFFFFFFu, local);
    if ((threadIdx.x & 31) == 0 && m) atomicAdd(cnt, __popc(m));
}
// fused: edge conversion + degree histogram
__global__ void ei_hist_kernel(const void* __restrict__ ei, int* __restrict__ src,
                               int* __restrict__ dst, const int* __restrict__ cnt,
                               int* __restrict__ degi) {
    int e = blockIdx.x * blockDim.x + threadIdx.x;
    if (e >= N_EDGES) return;
    int s, d;
    if (*cnt < 100) { const long long* p = (const long long*)ei; s = (int)p[e]; d = (int)p[N_EDGES + e]; }
    else            { const int* p = (const int*)ei;             s = p[e];      d = p[N_EDGES + e]; }
    s = min(max(s, 0), N_NODES - 1);
    d = min(max(d, 0), N_NODES - 1);
    src[e] = s;
    dst[e] = d;
    atomicAdd(&degi[d], 1);
}
// fused: batch conversion + dinv
__global__ void bat_dinv_kernel(const void* __restrict__ bat, int* __restrict__ batch,
                                const int* __restrict__ cnt,
                                const int* __restrict__ degi, float* __restrict__ dinv) {
    int i = blockIdx.x * blockDim.x + threadIdx.x;
    if (i >= N_NODES) return;
    int g;
    if (*cnt < 100) g = (int)((const long long*)bat)[i];
    else            g = ((const int*)bat)[i];
    batch[i] = min(max(g, 0), N_GRAPHS - 1);
    dinv[i] = rsqrtf((float)degi[i] + 1.0f);
}

// ---------------- weight transpose + fp16 convert (both weights) -------------
__global__ void conv_w_kernel(const float* __restrict__ W1, const float* __restrict__ W2,
                              __half* __restrict__ w1t, __half* __restrict__ w2t) {
    int i = blockIdx.x * blockDim.x + threadIdx.x;
    if (i < HID * IN_CH) {
        int n = i / IN_CH, k = i % IN_CH;
        w1t[(size_t)n * IN_CH + k] = __float2half_rn(W1[(size_t)k * HID + n]);
    } else {
        int j = i - HID * IN_CH;
        if (j < OUT_CH * HID) {
            int n = j / HID, k = j % HID;
            w2t[(size_t)n * HID + k] = __float2half_rn(W2[(size_t)k * OUT_CH + n]);
        }
    }
}

// ---------------- CSR scan ----------------------------------------------------
__global__ __launch_bounds__(SCAN_BLK) void scan1_kernel(
    const int* __restrict__ degi, int* __restrict__ offs, int* __restrict__ partials) {
    __shared__ int sm[SCAN_BLK];
    int i = blockIdx.x * SCAN_BLK + threadIdx.x;
    int v = (i < N_NODES) ? degi[i] : 0;
    sm[threadIdx.x] = v;
    __syncthreads();
    for (int d = 1; d < SCAN_BLK; d <<= 1) {
        int t = (threadIdx.x >= d) ? sm[threadIdx.x - d] : 0;
        __syncthreads();
        sm[threadIdx.x] += t;
        __syncthreads();
    }
    if (i < N_NODES) offs[i] = sm[threadIdx.x] - v;       // exclusive
    if (threadIdx.x == SCAN_BLK - 1) partials[blockIdx.x] = sm[SCAN_BLK - 1];
}
__global__ void scan2_kernel(int* partials) {
    if (threadIdx.x == 0 && blockIdx.x == 0) {
        int run = 0;
        for (int b = 0; b < SCAN_NB; b++) { int v = partials[b]; partials[b] = run; run += v; }
    }
}
__global__ void scan3_kernel(int* __restrict__ offs, int* __restrict__ cursor,
                             const int* __restrict__ partials) {
    int i = blockIdx.x * blockDim.x + threadIdx.x;
    if (i < N_NODES) {
        int o = offs[i] + partials[i / SCAN_BLK];
        offs[i] = o;
        cursor[i] = o;
    }
}
__global__ void scatter_build_kernel(const int* __restrict__ src, const int* __restrict__ dst,
                                     int* __restrict__ cursor, int* __restrict__ ssrc) {
    int e = blockIdx.x * blockDim.x + threadIdx.x;
    if (e >= N_EDGES) return;
    int pos = atomicAdd(&cursor[dst[e]], 1);
    ssrc[pos] = src[e];
}

// ---------------- HMMA GEMM: C[Mpad,NT] = A[Mpad,256] @ Wt[NT,256]^T --------
// Single-pass fp16, fp32 accumulate, fp16 output. CTA tile 128x128, BK=32,
// register-staged double buffering. 8 warps = 4(M)x2(N); warp tile 32x64.
// AFP32: A fp32, rounded to fp16 on the STS path. Else A pre-converted fp16.
#define PADK 40
template <int NT, bool AFP32>
__global__ __launch_bounds__(256) void mma_gemm_kernel(
    const void* __restrict__ A_,
    const __half* __restrict__ B,
    __half* __restrict__ C)
{
    constexpr int K = 256;
    __shared__ __align__(16) __half sA[128 * PADK];
    __shared__ __align__(16) __half sB[128 * PADK];

    const int tid  = threadIdx.x;
    const int lane = tid & 31;
    const int wid  = tid >> 5;
    const int wm   = wid & 3;
    const int wn   = wid >> 2;
    const int bm   = blockIdx.y * 128;
    const int bn   = blockIdx.x * 128;

    const int r0l = tid >> 2, i0l = (tid & 3) * 8;
    const int r1l = r0l + 64;

    float acc[2][8][4];
    #pragma unroll
    for (int mt = 0; mt < 2; mt++)
        #pragma unroll
        for (int nt = 0; nt < 8; nt++)
            #pragma unroll
            for (int j = 0; j < 4; j++) acc[mt][nt][j] = 0.0f;

    const int qr = lane >> 2;
    const int qc = (lane & 3) * 2;

    float4 pAf[2][2];
    uint4  pA[2];
    uint4  pB[2];

    auto prefetch = [&](int kc) {
        if constexpr (AFP32) {
            const float* A = (const float*)A_;
            #pragma unroll
            for (int it = 0; it < 2; it++) {
                int r = (it == 0) ? r0l : r1l;
                if (bm + r < N_NODES) {
                    size_t gi = (size_t)(bm + r) * K + kc + i0l;
                    pAf[it][0] = *(const float4*)(A + gi);
                    pAf[it][1] = *(const float4*)(A + gi + 4);
                } else {
                    pAf[it][0] = make_float4(0.f, 0.f, 0.f, 0.f);
                    pAf[it][1] = make_float4(0.f, 0.f, 0.f, 0.f);
                }
            }
        } else {
            const __half* A = (const __half*)A_;
            #pragma unroll
            for (int it = 0; it < 2; it++) {
                int r = (it == 0) ? r0l : r1l;
                size_t gi = (size_t)(bm + r) * K + kc + i0l;
                pA[it] = *(const uint4*)(A + gi);
            }
        }
        #pragma unroll
        for (int it = 0; it < 2; it++) {
            int r = (it == 0) ? r0l : r1l;
            size_t gi = (size_t)(bn + r) * K + kc + i0l;
            pB[it] = *(const uint4*)(B + gi);
        }
    };

    auto stage = [&]() {
        if constexpr (AFP32) {
            #pragma unroll
            for (int it = 0; it < 2; it++) {
                int r = (it == 0) ? r0l : r1l;
                uint4 v;
                v.x = pack_h2(pAf[it][0].x, pAf[it][0].y);
                v.y = pack_h2(pAf[it][0].z, pAf[it][0].w);
                v.z = pack_h2(pAf[it][1].x, pAf[it][1].y);
                v.w = pack_h2(pAf[it][1].z, pAf[it][1].w);
                *(uint4*)&sA[r * PADK + i0l] = v;
            }
        } else {
            #pragma unroll
            for (int it = 0; it < 2; it++) {
                int r = (it == 0) ? r0l : r1l;
                *(uint4*)&sA[r * PADK + i0l] = pA[it];
            }
        }
        #pragma unroll
        for (int it = 0; it < 2; it++) {
            int r = (it == 0) ? r0l : r1l;
            *(uint4*)&sB[r * PADK + i0l] = pB[it];
        }
    };

    prefetch(0);
    for (int kc = 0; kc < K; kc += 32) {
        stage();
        __syncthreads();
        if (kc + 32 < K) prefetch(kc + 32);   // LDGs overlap with MMAs below

        #pragma unroll
        for (int ks = 0; ks < 2; ks++) {
            const int kb = ks * 16;
            uint32_t ah[2][4];
            #pragma unroll
            for (int mt = 0; mt < 2; mt++) {
                int rr = wm * 32 + mt * 16 + qr;
                #pragma unroll
                for (int h = 0; h < 2; h++) {
                    int r = rr + h * 8;
                    ah[mt][h]     = *(const uint32_t*)&sA[r * PADK + kb + qc];
                    ah[mt][h + 2] = *(const uint32_t*)&sA[r * PADK + kb + qc + 8];
                }
            }
            #pragma unroll
            for (int nt = 0; nt < 8; nt++) {
                int n = wn * 64 + nt * 8 + qr;
                uint32_t b0 = *(const uint32_t*)&sB[n * PADK + kb + qc];
                uint32_t b1 = *(const uint32_t*)&sB[n * PADK + kb + qc + 8];
                #pragma unroll
                for (int mt = 0; mt < 2; mt++)
                    mma_f16(acc[mt][nt], ah[mt][0], ah[mt][1], ah[mt][2], ah[mt][3],
                            b0, b1);
            }
        }
        __syncthreads();
    }

    // fp16 epilogue: c0,c1 -> (row, col..col+1); c2,c3 -> (row+8, ...)
    #pragma unroll
    for (int mt = 0; mt < 2; mt++) {
        #pragma unroll
        for (int nt = 0; nt < 8; nt++) {
            int r0 = bm + wm * 32 + mt * 16 + qr;
            int c0 = bn + wn * 64 + nt * 8 + qc;
            *(uint32_t*)(C + (size_t)r0 * NT + c0) = pack_h2(acc[mt][nt][0], acc[mt][nt][1]);
            *(uint32_t*)(C + (size_t)(r0 + 8) * NT + c0) = pack_h2(acc[mt][nt][2], acc[mt][nt][3]);
        }
    }
}

// ---------------- CSR gather aggregation (fp16 features) ---------------------
// MODE 0 (layer 1, F=256): lane owns 8 cols (uint4);  out fp16 a2
// MODE 1 (layer 2, F=128): lane owns 4 cols (uint2);  red-add into sums
template <int F, int MODE>
__global__ __launch_bounds__(128) void gather_kernel(
    const int* __restrict__ offs, const int* __restrict__ degi,
    const int* __restrict__ ssrc, const float* __restrict__ dinv,
    const __half* __restrict__ h, const float* __restrict__ bias,
    __half* __restrict__ oh,
    const int* __restrict__ batch, float* __restrict__ sums,
    int* __restrict__ counts)
{
    constexpr int HPL = F / 32;                   // halves per lane: 8 or 4
    int node = blockIdx.x * 4 + (threadIdx.x >> 5);
    int lane = threadIdx.x & 31;
    if (node >= N_NODES) return;

    int start = offs[node];
    int dg    = degi[node];
    float dn  = dinv[node];

    float acc[HPL];
    #pragma unroll
    for (int v = 0; v < HPL; v++) acc[v] = 0.0f;

    auto accum = [&](int s, float w) {
        if constexpr (HPL == 8) {
            uint4 v = __ldg((const uint4*)(h + (size_t)s * F) + lane);
            const __half2* hp = (const __half2*)&v;
            #pragma unroll
            for (int i = 0; i < 4; i++) {
                float2 f = __half22float2(hp[i]);
                acc[2 * i]     += w * f.x;
                acc[2 * i + 1] += w * f.y;
            }
        } else {
            uint2 v = __ldg((const uint2*)(h + (size_t)s * F) + lane);
            const __half2* hp = (const __half2*)&v;
            #pragma unroll
            for (int i = 0; i < 2; i++) {
                float2 f = __half22float2(hp[i]);
                acc[2 * i]     += w * f.x;
                acc[2 * i + 1] += w * f.y;
            }
        }
    };

    int j = 0;
    for (; j + 2 <= dg; j += 2) {
        int s0 = __ldg(&ssrc[start + j]);
        int s1 = __ldg(&ssrc[start + j + 1]);
        float w0 = __ldg(&dinv[s0]) * dn;
        float w1 = __ldg(&dinv[s1]) * dn;
        accum(s0, w0);
        accum(s1, w1);
    }
    if (j < dg) {
        int s0 = __ldg(&ssrc[start + j]);
        accum(s0, __ldg(&dinv[s0]) * dn);
    }

    float sl = dn * dn;      // 1/deg (self-loop weight)
    int col = lane * HPL;
    // self term
    float selfv[HPL];
    if constexpr (HPL == 8) {
        uint4 v = __ldg((const uint4*)(h + (size_t)node * F) + lane);
        const __half2* hp = (const __half2*)&v;
        #pragma unroll
        for (int i = 0; i < 4; i++) {
            float2 f = __half22float2(hp[i]);
            selfv[2 * i] = f.x; selfv[2 * i + 1] = f.y;
        }
    } else {
        uint2 v = __ldg((const uint2*)(h + (size_t)node * F) + lane);
        const __half2* hp = (const __half2*)&v;
        #pragma unroll
        for (int i = 0; i < 2; i++) {
            float2 f = __half22float2(hp[i]);
            selfv[2 * i] = f.x; selfv[2 * i + 1] = f.y;
        }
    }

    if constexpr (MODE == 0) {
        uint32_t outw[HPL / 2];
        #pragma unroll
        for (int i = 0; i < HPL; i += 2) {
            float r0 = acc[i]     + selfv[i]     * sl + bias[col + i];
            float r1 = acc[i + 1] + selfv[i + 1] * sl + bias[col + i + 1];
            r0 = r0 > 0.f ? r0 : expm1f(r0);
            r1 = r1 > 0.f ? r1 : expm1f(r1);
            outw[i / 2] = pack_h2(r0, r1);
        }
        *(uint4*)(oh + (size_t)node * F + col) =
            make_uint4(outw[0], outw[1], outw[2], outw[3]);
    } else {
        int g = batch[node];
        float4 bv = *(const float4*)(bias + col);
        float4 r = make_float4(acc[0] + selfv[0] * sl + bv.x,
                               acc[1] + selfv[1] * sl + bv.y,
                               acc[2] + selfv[2] * sl + bv.z,
                               acc[3] + selfv[3] * sl + bv.w);
        red_add_v4(sums + g * F + col, r);
        if (lane == 0) atomicAdd(&counts[g], 1);
    }
}

__global__ void pool_final_kernel(const float* __restrict__ sums,
                                  const int* __restrict__ counts,
                                  float* __restrict__ out)
{
    int c = blockIdx.x * blockDim.x + threadIdx.x;
    if (c < N_GRAPHS * OUT_CH) {
        int g = c / OUT_CH;
        float cnt = fmaxf((float)counts[g], 1.0f);
        out[c] = sums[c] / cnt;
    }
}

__global__ void zero_out_kernel(float* out, int n) {
    int i = blockIdx.x * blockDim.x + threadIdx.x;
    if (i < n) out[i] = 0.0f;
}

// ---------------- launch -----------------------------------------------------
extern "C" void kernel_launch(void* const* d_in, const int* in_sizes, int n_in,
                              void* d_out, int out_size)
{
    const float* x   = nullptr;
    const float* W1  = nullptr;
    const float* b1  = nullptr;
    const float* W2  = nullptr;
    const float* b2  = nullptr;
    const void*  ei  = nullptr;
    const void*  bat = nullptr;

    for (int i = 0; i < n_in; i++) {
        switch (in_sizes[i]) {
            case 12800000: x   = (const float*)d_in[i]; break;
            case 65536:    W1  = (const float*)d_in[i]; break;
            case 256:      b1  = (const float*)d_in[i]; break;
            case 32768:    W2  = (const float*)d_in[i]; break;
            case 128:      b2  = (const float*)d_in[i]; break;
            case 1600000:  ei  = d_in[i];               break;
            case 50000:    bat = d_in[i];               break;
            default: break;
        }
    }
    float* out = (float*)d_out;

    if (!x || !W1 || !b1 || !W2 || !b2 || !ei || !bat) {
        zero_out_kernel<<<(out_size + 255) / 256, 256>>>(out, out_size);
        return;
    }

    void* p;
    cudaGetSymbolAddress(&p, g_dinv);    float* dinv   = (float*)p;
    cudaGetSymbolAddress(&p, g_degi);    int*   degi   = (int*)p;
    cudaGetSymbolAddress(&p, g_offs);    int*   offs   = (int*)p;
    cudaGetSymbolAddress(&p, g_cursor);  int*   cursor = (int*)p;
    cudaGetSymbolAddress(&p, g_partials);int*   parts  = (int*)p;
    cudaGetSymbolAddress(&p, g_ssrc);    int*   ssrc   = (int*)p;
    cudaGetSymbolAddress(&p, g_h1);      __half* h1    = (__half*)p;
    cudaGetSymbolAddress(&p, g_h2);      __half* h2    = (__half*)p;
    cudaGetSymbolAddress(&p, g_sums);    float* sums   = (float*)p;
    cudaGetSymbolAddress(&p, g_counts);  int*   counts = (int*)p;
    cudaGetSymbolAddress(&p, g_src);     int*   src    = (int*)p;
    cudaGetSymbolAddress(&p, g_dst);     int*   dst    = (int*)p;
    cudaGetSymbolAddress(&p, g_batch);   int*   batch  = (int*)p;
    cudaGetSymbolAddress(&p, g_odd_ei);  int*   oddei  = (int*)p;
    cudaGetSymbolAddress(&p, g_odd_bat); int*   oddbat = (int*)p;
    cudaGetSymbolAddress(&p, g_a2);      __half* a2    = (__half*)p;
    cudaGetSymbolAddress(&p, g_w1t);     __half* w1t   = (__half*)p;
    cudaGetSymbolAddress(&p, g_w2t);     __half* w2t   = (__half*)p;

    cudaMemsetAsync(degi,   0, N_NODES * sizeof(int));
    cudaMemsetAsync(sums,   0, N_GRAPHS * OUT_CH * sizeof(float));
    cudaMemsetAsync(counts, 0, N_GRAPHS * sizeof(int));
    cudaMemsetAsync(oddei,  0, sizeof(int));
    cudaMemsetAsync(oddbat, 0, sizeof(int));

    // dtype detection
    detect_kernel<<<(1600000 / 2 + 255) / 256, 256>>>((const int*)ei, 1600000, oddei);
    detect_kernel<<<(50000 / 2 + 255) / 256, 256>>>((const int*)bat, 50000, oddbat);

    // edge conversion + degree histogram (fused)
    ei_hist_kernel<<<(N_EDGES + 255) / 256, 256>>>(ei, src, dst, oddei, degi);
    // batch conversion + dinv (fused)
    bat_dinv_kernel<<<(N_NODES + 255) / 256, 256>>>(bat, batch, oddbat, degi, dinv);

    // CSR offsets
    scan1_kernel<<<SCAN_NB, SCAN_BLK>>>(degi, offs, parts);
    scan2_kernel<<<1, 32>>>(parts);
    scan3_kernel<<<(N_NODES + 255) / 256, 256>>>(offs, cursor, parts);
    scatter_build_kernel<<<(N_EDGES + 255) / 256, 256>>>(src, dst, cursor, ssrc);

    // weight transpose + fp16 (both weights, one kernel)
    conv_w_kernel<<<(HID * IN_CH + OUT_CH * HID + 255) / 256, 256>>>(W1, W2, w1t, w2t);

    // h1 = x @ W1  (fp16 HMMA, fp32 A rounded in-kernel, fp16 out)
    mma_gemm_kernel<HID, true><<<dim3(HID / 128, N_PAD / 128), 256>>>(x, w1t, h1);

    // layer-1 gather + ELU + bias -> fp16 a2
    gather_kernel<HID, 0><<<(N_NODES + 3) / 4, 128>>>(
        offs, degi, ssrc, dinv, h1, b1, a2, nullptr, nullptr, nullptr);

    // h2 = a2 @ W2  (fp16 HMMA, fp16 out)
    mma_gemm_kernel<OUT_CH, false><<<dim3(OUT_CH / 128, N_PAD / 128), 256>>>(a2, w2t, h2);

    // layer-2 gather + bias + mean-pool accumulate
    gather_kernel<OUT_CH, 1><<<(N_NODES + 3) / 4, 128>>>(
        offs, degi, ssrc, dinv, h2, b2, nullptr, batch, sums, counts);

    pool_final_kernel<<<(N_GRAPHS * OUT_CH + 255) / 256, 256>>>(sums, counts, out);
}

// round 10
// speedup vs baseline: 2.8361x; 1.0029x over previous
#include <cuda_runtime.h>
#include <cuda_fp16.h>
#include <cstdint>

#define N_NODES 50000
#define N_PAD   50048      // multiple of 128 for MMA tiles
#define N_EDGES 800000
#define IN_CH 256
#define HID 256
#define OUT_CH 128
#define N_GRAPHS 64
#define SCAN_BLK 512
#define SCAN_NB  ((N_NODES + SCAN_BLK - 1) / SCAN_BLK)   // 98

// ---------------- scratch (device globals; no cudaMalloc allowed) ----------
__device__ float g_dinv[N_NODES];
__device__ int   g_degi[N_NODES];
__device__ int   g_offs[N_NODES];
__device__ int   g_cursor[N_NODES];
__device__ int   g_partials[SCAN_NB];
__device__ int   g_ssrc[N_EDGES];
__device__ __half g_h1[(size_t)N_PAD * HID];
__device__ __half g_h2[(size_t)N_PAD * OUT_CH];
__device__ float g_sums[N_GRAPHS * OUT_CH];
__device__ int   g_counts[N_GRAPHS];
__device__ int   g_src[N_EDGES];
__device__ int   g_dst[N_EDGES];
__device__ int   g_batch[N_NODES];
__device__ int   g_oddcnt[2];             // [0]=edge_index, [1]=batch
// fp16 operands. Pad rows (>= N_NODES) of g_a2 stay zero: zero-initialized
// device globals, never written.
__device__ __half g_a2[(size_t)N_PAD * HID];
__device__ __half g_w1t[HID * IN_CH];     // [n][k] = W1[k][n]
__device__ __half g_w2t[OUT_CH * HID];

// ---------------- helpers ---------------------------------------------------
__device__ __forceinline__ void red_add_v4(float* addr, float4 v) {
    asm volatile("red.global.add.v4.f32 [%0], {%1,%2,%3,%4};"
                 :: "l"(addr), "f"(v.x), "f"(v.y), "f"(v.z), "f"(v.w) : "memory");
}
__device__ __forceinline__ void mma_f16(float* c, uint32_t a0, uint32_t a1,
                                        uint32_t a2, uint32_t a3,
                                        uint32_t b0, uint32_t b1) {
    asm volatile("mma.sync.aligned.m16n8k16.row.col.f32.f16.f16.f32 "
                 "{%0,%1,%2,%3}, {%4,%5,%6,%7}, {%8,%9}, {%0,%1,%2,%3};"
                 : "+f"(c[0]), "+f"(c[1]), "+f"(c[2]), "+f"(c[3])
                 : "r"(a0), "r"(a1), "r"(a2), "r"(a3), "r"(b0), "r"(b1));
}
__device__ __forceinline__ uint32_t pack_h2(float a, float b) {
    __half2 h = __floats2half2_rn(a, b);
    return *reinterpret_cast<uint32_t*>(&h);
}

// ---------------- dtype detection (both buffers, one kernel) -----------------
// Thread ranges are warp-aligned (800000 and 25000+pad), so `which` is warp-uniform.
__global__ void detect_kernel(const int* __restrict__ ei32, const int* __restrict__ bat32,
                              int* __restrict__ cnt) {
    int i = blockIdx.x * blockDim.x + threadIdx.x;
    int local = 0, which = -1;
    if (i < 800000)       { which = 0; local = (ei32[2 * i + 1] != 0); }
    else if (i < 825000)  { which = 1; local = (bat32[2 * (i - 800000) + 1] != 0); }
    unsigned m = __ballot_sync(0xFFFFFFFFu, local);
    if ((threadIdx.x & 31) == 0 && m && which >= 0) atomicAdd(&cnt[which], __popc(m));
}
// fused: edge conversion + degree histogram
__global__ void ei_hist_kernel(const void* __restrict__ ei, int* __restrict__ src,
                               int* __restrict__ dst, const int* __restrict__ cnt,
                               int* __restrict__ degi) {
    int e = blockIdx.x * blockDim.x + threadIdx.x;
    if (e >= N_EDGES) return;
    int s, d;
    if (cnt[0] < 100) { const long long* p = (const long long*)ei; s = (int)p[e]; d = (int)p[N_EDGES + e]; }
    else              { const int* p = (const int*)ei;             s = p[e];      d = p[N_EDGES + e]; }
    s = min(max(s, 0), N_NODES - 1);
    d = min(max(d, 0), N_NODES - 1);
    src[e] = s;
    dst[e] = d;
    atomicAdd(&degi[d], 1);
}
// fused: batch conversion + dinv
__global__ void bat_dinv_kernel(const void* __restrict__ bat, int* __restrict__ batch,
                                const int* __restrict__ cnt,
                                const int* __restrict__ degi, float* __restrict__ dinv) {
    int i = blockIdx.x * blockDim.x + threadIdx.x;
    if (i >= N_NODES) return;
    int g;
    if (cnt[1] < 100) g = (int)((const long long*)bat)[i];
    else              g = ((const int*)bat)[i];
    batch[i] = min(max(g, 0), N_GRAPHS - 1);
    dinv[i] = rsqrtf((float)degi[i] + 1.0f);
}

// ---------------- weight transpose + fp16 convert (both weights) -------------
__global__ void conv_w_kernel(const float* __restrict__ W1, const float* __restrict__ W2,
                              __half* __restrict__ w1t, __half* __restrict__ w2t) {
    int i = blockIdx.x * blockDim.x + threadIdx.x;
    if (i < HID * IN_CH) {
        int n = i / IN_CH, k = i % IN_CH;
        w1t[(size_t)n * IN_CH + k] = __float2half_rn(W1[(size_t)k * HID + n]);
    } else {
        int j = i - HID * IN_CH;
        if (j < OUT_CH * HID) {
            int n = j / HID, k = j % HID;
            w2t[(size_t)n * HID + k] = __float2half_rn(W2[(size_t)k * OUT_CH + n]);
        }
    }
}

// ---------------- CSR scan ----------------------------------------------------
__global__ __launch_bounds__(SCAN_BLK) void scan1_kernel(
    const int* __restrict__ degi, int* __restrict__ offs, int* __restrict__ partials) {
    __shared__ int sm[SCAN_BLK];
    int i = blockIdx.x * SCAN_BLK + threadIdx.x;
    int v = (i < N_NODES) ? degi[i] : 0;
    sm[threadIdx.x] = v;
    __syncthreads();
    for (int d = 1; d < SCAN_BLK; d <<= 1) {
        int t = (threadIdx.x >= d) ? sm[threadIdx.x - d] : 0;
        __syncthreads();
        sm[threadIdx.x] += t;
        __syncthreads();
    }
    if (i < N_NODES) offs[i] = sm[threadIdx.x] - v;       // exclusive
    if (threadIdx.x == SCAN_BLK - 1) partials[blockIdx.x] = sm[SCAN_BLK - 1];
}
// single-warp shfl scan over SCAN_NB partials (exclusive)
__global__ void scan2_kernel(int* __restrict__ partials) {
    int lane = threadIdx.x;
    int run = 0;
    for (int b = 0; b < SCAN_NB; b += 32) {
        int idx = b + lane;
        int orig = (idx < SCAN_NB) ? partials[idx] : 0;
        int v = orig;
        #pragma unroll
        for (int d = 1; d < 32; d <<= 1) {
            int t = __shfl_up_sync(0xFFFFFFFFu, v, d);
            if (lane >= d) v += t;
        }
        if (idx < SCAN_NB) partials[idx] = run + v - orig;   // exclusive
        run += __shfl_sync(0xFFFFFFFFu, v, 31);
    }
}
__global__ void scan3_kernel(int* __restrict__ offs, int* __restrict__ cursor,
                             const int* __restrict__ partials) {
    int i = blockIdx.x * blockDim.x + threadIdx.x;
    if (i < N_NODES) {
        int o = offs[i] + partials[i / SCAN_BLK];
        offs[i] = o;
        cursor[i] = o;
    }
}
__global__ void scatter_build_kernel(const int* __restrict__ src, const int* __restrict__ dst,
                                     int* __restrict__ cursor, int* __restrict__ ssrc) {
    int e = blockIdx.x * blockDim.x + threadIdx.x;
    if (e >= N_EDGES) return;
    int pos = atomicAdd(&cursor[dst[e]], 1);
    ssrc[pos] = src[e];
}

// ---------------- HMMA GEMM: C[Mpad,NT] = A[Mpad,256] @ Wt[NT,256]^T --------
// Single-pass fp16, fp32 accumulate, fp16 output. CTA tile 128x128, BK=32,
// register-staged double buffering. 8 warps = 4(M)x2(N); warp tile 32x64.
// AFP32: A fp32, rounded to fp16 on the STS path. Else A pre-converted fp16.
#define PADK 40
template <int NT, bool AFP32>
__global__ __launch_bounds__(256) void mma_gemm_kernel(
    const void* __restrict__ A_,
    const __half* __restrict__ B,
    __half* __restrict__ C)
{
    constexpr int K = 256;
    __shared__ __align__(16) __half sA[128 * PADK];
    __shared__ __align__(16) __half sB[128 * PADK];

    const int tid  = threadIdx.x;
    const int lane = tid & 31;
    const int wid  = tid >> 5;
    const int wm   = wid & 3;
    const int wn   = wid >> 2;
    const int bm   = blockIdx.y * 128;
    const int bn   = blockIdx.x * 128;

    const int r0l = tid >> 2, i0l = (tid & 3) * 8;
    const int r1l = r0l + 64;

    float acc[2][8][4];
    #pragma unroll
    for (int mt = 0; mt < 2; mt++)
        #pragma unroll
        for (int nt = 0; nt < 8; nt++)
            #pragma unroll
            for (int j = 0; j < 4; j++) acc[mt][nt][j] = 0.0f;

    const int qr = lane >> 2;
    const int qc = (lane & 3) * 2;

    float4 pAf[2][2];
    uint4  pA[2];
    uint4  pB[2];

    auto prefetch = [&](int kc) {
        if constexpr (AFP32) {
            const float* A = (const float*)A_;
            #pragma unroll
            for (int it = 0; it < 2; it++) {
                int r = (it == 0) ? r0l : r1l;
                if (bm + r < N_NODES) {
                    size_t gi = (size_t)(bm + r) * K + kc + i0l;
                    pAf[it][0] = *(const float4*)(A + gi);
                    pAf[it][1] = *(const float4*)(A + gi + 4);
                } else {
                    pAf[it][0] = make_float4(0.f, 0.f, 0.f, 0.f);
                    pAf[it][1] = make_float4(0.f, 0.f, 0.f, 0.f);
                }
            }
        } else {
            const __half* A = (const __half*)A_;
            #pragma unroll
            for (int it = 0; it < 2; it++) {
                int r = (it == 0) ? r0l : r1l;
                size_t gi = (size_t)(bm + r) * K + kc + i0l;
                pA[it] = *(const uint4*)(A + gi);
            }
        }
        #pragma unroll
        for (int it = 0; it < 2; it++) {
            int r = (it == 0) ? r0l : r1l;
            size_t gi = (size_t)(bn + r) * K + kc + i0l;
            pB[it] = *(const uint4*)(B + gi);
        }
    };

    auto stage = [&]() {
        if constexpr (AFP32) {
            #pragma unroll
            for (int it = 0; it < 2; it++) {
                int r = (it == 0) ? r0l : r1l;
                uint4 v;
                v.x = pack_h2(pAf[it][0].x, pAf[it][0].y);
                v.y = pack_h2(pAf[it][0].z, pAf[it][0].w);
                v.z = pack_h2(pAf[it][1].x, pAf[it][1].y);
                v.w = pack_h2(pAf[it][1].z, pAf[it][1].w);
                *(uint4*)&sA[r * PADK + i0l] = v;
            }
        } else {
            #pragma unroll
            for (int it = 0; it < 2; it++) {
                int r = (it == 0) ? r0l : r1l;
                *(uint4*)&sA[r * PADK + i0l] = pA[it];
            }
        }
        #pragma unroll
        for (int it = 0; it < 2; it++) {
            int r = (it == 0) ? r0l : r1l;
            *(uint4*)&sB[r * PADK + i0l] = pB[it];
        }
    };

    prefetch(0);
    for (int kc = 0; kc < K; kc += 32) {
        stage();
        __syncthreads();
        if (kc + 32 < K) prefetch(kc + 32);   // LDGs overlap with MMAs below

        #pragma unroll
        for (int ks = 0; ks < 2; ks++) {
            const int kb = ks * 16;
            uint32_t ah[2][4];
            #pragma unroll
            for (int mt = 0; mt < 2; mt++) {
                int rr = wm * 32 + mt * 16 + qr;
                #pragma unroll
                for (int h = 0; h < 2; h++) {
                    int r = rr + h * 8;
                    ah[mt][h]     = *(const uint32_t*)&sA[r * PADK + kb + qc];
                    ah[mt][h + 2] = *(const uint32_t*)&sA[r * PADK + kb + qc + 8];
                }
            }
            #pragma unroll
            for (int nt = 0; nt < 8; nt++) {
                int n = wn * 64 + nt * 8 + qr;
                uint32_t b0 = *(const uint32_t*)&sB[n * PADK + kb + qc];
                uint32_t b1 = *(const uint32_t*)&sB[n * PADK + kb + qc + 8];
                #pragma unroll
                for (int mt = 0; mt < 2; mt++)
                    mma_f16(acc[mt][nt], ah[mt][0], ah[mt][1], ah[mt][2], ah[mt][3],
                            b0, b1);
            }
        }
        __syncthreads();
    }

    #pragma unroll
    for (int mt = 0; mt < 2; mt++) {
        #pragma unroll
        for (int nt = 0; nt < 8; nt++) {
            int r0 = bm + wm * 32 + mt * 16 + qr;
            int c0 = bn + wn * 64 + nt * 8 + qc;
            *(uint32_t*)(C + (size_t)r0 * NT + c0) = pack_h2(acc[mt][nt][0], acc[mt][nt][1]);
            *(uint32_t*)(C + (size_t)(r0 + 8) * NT + c0) = pack_h2(acc[mt][nt][2], acc[mt][nt][3]);
        }
    }
}

// ---------------- CSR gather aggregation (fp16 features) ---------------------
// Warp per node. Per 32-edge chunk: coalesced lane-parallel load of indices +
// weights, then shfl-broadcast per edge -> the only per-edge load is the h row.
// MODE 0 (layer 1, F=256): lane owns 8 cols (uint4);  out fp16 a2
// MODE 1 (layer 2, F=128): lane owns 4 cols (uint2);  red-add into sums
template <int F, int MODE>
__global__ __launch_bounds__(128) void gather_kernel(
    const int* __restrict__ offs, const int* __restrict__ degi,
    const int* __restrict__ ssrc, const float* __restrict__ dinv,
    const __half* __restrict__ h, const float* __restrict__ bias,
    __half* __restrict__ oh,
    const int* __restrict__ batch, float* __restrict__ sums,
    int* __restrict__ counts)
{
    constexpr int HPL = F / 32;                   // halves per lane: 8 or 4
    int node = blockIdx.x * 4 + (threadIdx.x >> 5);
    int lane = threadIdx.x & 31;
    if (node >= N_NODES) return;

    int start = offs[node];
    int dg    = degi[node];
    float dn  = dinv[node];

    float acc[HPL];
    #pragma unroll
    for (int v = 0; v < HPL; v++) acc[v] = 0.0f;

    auto accum = [&](int s, float w) {
        if constexpr (HPL == 8) {
            uint4 v = __ldg((const uint4*)(h + (size_t)s * F) + lane);
            const __half2* hp = (const __half2*)&v;
            #pragma unroll
            for (int i = 0; i < 4; i++) {
                float2 f = __half22float2(hp[i]);
                acc[2 * i]     += w * f.x;
                acc[2 * i + 1] += w * f.y;
            }
        } else {
            uint2 v = __ldg((const uint2*)(h + (size_t)s * F) + lane);
            const __half2* hp = (const __half2*)&v;
            #pragma unroll
            for (int i = 0; i < 2; i++) {
                float2 f = __half22float2(hp[i]);
                acc[2 * i]     += w * f.x;
                acc[2 * i + 1] += w * f.y;
            }
        }
    };

    for (int base = 0; base < dg; base += 32) {
        int nch = min(32, dg - base);
        int   s_l = 0;
        float w_l = 0.0f;
        if (lane < nch) {
            s_l = __ldg(&ssrc[start + base + lane]);     // one coalesced LDG
            w_l = __ldg(&dinv[s_l]) * dn;                // parallel gather
        }
        #pragma unroll 4
        for (int j = 0; j < nch; j++) {
            int   s = __shfl_sync(0xFFFFFFFFu, s_l, j);
            float w = __shfl_sync(0xFFFFFFFFu, w_l, j);
            accum(s, w);                                 // independent h-row loads
        }
    }

    float sl = dn * dn;      // 1/deg (self-loop weight)
    int col = lane * HPL;
    float selfv[HPL];
    if constexpr (HPL == 8) {
        uint4 v = __ldg((const uint4*)(h + (size_t)node * F) + lane);
        const __half2* hp = (const __half2*)&v;
        #pragma unroll
        for (int i = 0; i < 4; i++) {
            float2 f = __half22float2(hp[i]);
            selfv[2 * i] = f.x; selfv[2 * i + 1] = f.y;
        }
    } else {
        uint2 v = __ldg((const uint2*)(h + (size_t)node * F) + lane);
        const __half2* hp = (const __half2*)&v;
        #pragma unroll
        for (int i = 0; i < 2; i++) {
            float2 f = __half22float2(hp[i]);
            selfv[2 * i] = f.x; selfv[2 * i + 1] = f.y;
        }
    }

    if constexpr (MODE == 0) {
        uint32_t outw[HPL / 2];
        #pragma unroll
        for (int i = 0; i < HPL; i += 2) {
            float r0 = acc[i]     + selfv[i]     * sl + bias[col + i];
            float r1 = acc[i + 1] + selfv[i + 1] * sl + bias[col + i + 1];
            r0 = r0 > 0.f ? r0 : expm1f(r0);
            r1 = r1 > 0.f ? r1 : expm1f(r1);
            outw[i / 2] = pack_h2(r0, r1);
        }
        *(uint4*)(oh + (size_t)node * F + col) =
            make_uint4(outw[0], outw[1], outw[2], outw[3]);
    } else {
        int g = batch[node];
        float4 bv = *(const float4*)(bias + col);
        float4 r = make_float4(acc[0] + selfv[0] * sl + bv.x,
                               acc[1] + selfv[1] * sl + bv.y,
                               acc[2] + selfv[2] * sl + bv.z,
                               acc[3] + selfv[3] * sl + bv.w);
        red_add_v4(sums + g * F + col, r);
        if (lane == 0) atomicAdd(&counts[g], 1);
    }
}

__global__ void pool_final_kernel(const float* __restrict__ sums,
                                  const int* __restrict__ counts,
                                  float* __restrict__ out)
{
    int c = blockIdx.x * blockDim.x + threadIdx.x;
    if (c < N_GRAPHS * OUT_CH) {
        int g = c / OUT_CH;
        float cnt = fmaxf((float)counts[g], 1.0f);
        out[c] = sums[c] / cnt;
    }
}

__global__ void zero_out_kernel(float* out, int n) {
    int i = blockIdx.x * blockDim.x + threadIdx.x;
    if (i < n) out[i] = 0.0f;
}

// ---------------- launch -----------------------------------------------------
extern "C" void kernel_launch(void* const* d_in, const int* in_sizes, int n_in,
                              void* d_out, int out_size)
{
    const float* x   = nullptr;
    const float* W1  = nullptr;
    const float* b1  = nullptr;
    const float* W2  = nullptr;
    const float* b2  = nullptr;
    const void*  ei  = nullptr;
    const void*  bat = nullptr;

    for (int i = 0; i < n_in; i++) {
        switch (in_sizes[i]) {
            case 12800000: x   = (const float*)d_in[i]; break;
            case 65536:    W1  = (const float*)d_in[i]; break;
            case 256:      b1  = (const float*)d_in[i]; break;
            case 32768:    W2  = (const float*)d_in[i]; break;
            case 128:      b2  = (const float*)d_in[i]; break;
            case 1600000:  ei  = d_in[i];               break;
            case 50000:    bat = d_in[i];               break;
            default: break;
        }
    }
    float* out = (float*)d_out;

    if (!x || !W1 || !b1 || !W2 || !b2 || !ei || !bat) {
        zero_out_kernel<<<(out_size + 255) / 256, 256>>>(out, out_size);
        return;
    }

    void* p;
    cudaGetSymbolAddress(&p, g_dinv);    float* dinv   = (float*)p;
    cudaGetSymbolAddress(&p, g_degi);    int*   degi   = (int*)p;
    cudaGetSymbolAddress(&p, g_offs);    int*   offs   = (int*)p;
    cudaGetSymbolAddress(&p, g_cursor);  int*   cursor = (int*)p;
    cudaGetSymbolAddress(&p, g_partials);int*   parts  = (int*)p;
    cudaGetSymbolAddress(&p, g_ssrc);    int*   ssrc   = (int*)p;
    cudaGetSymbolAddress(&p, g_h1);      __half* h1    = (__half*)p;
    cudaGetSymbolAddress(&p, g_h2);      __half* h2    = (__half*)p;
    cudaGetSymbolAddress(&p, g_sums);    float* sums   = (float*)p;
    cudaGetSymbolAddress(&p, g_counts);  int*   counts = (int*)p;
    cudaGetSymbolAddress(&p, g_src);     int*   src    = (int*)p;
    cudaGetSymbolAddress(&p, g_dst);     int*   dst    = (int*)p;
    cudaGetSymbolAddress(&p, g_batch);   int*   batch  = (int*)p;
    cudaGetSymbolAddress(&p, g_oddcnt);  int*   oddc   = (int*)p;
    cudaGetSymbolAddress(&p, g_a2);      __half* a2    = (__half*)p;
    cudaGetSymbolAddress(&p, g_w1t);     __half* w1t   = (__half*)p;
    cudaGetSymbolAddress(&p, g_w2t);     __half* w2t   = (__half*)p;

    cudaMemsetAsync(degi,   0, N_NODES * sizeof(int));
    cudaMemsetAsync(sums,   0, N_GRAPHS * OUT_CH * sizeof(float));
    cudaMemsetAsync(counts, 0, N_GRAPHS * sizeof(int));
    cudaMemsetAsync(oddc,   0, 2 * sizeof(int));

    // dtype detection (both buffers, one kernel)
    detect_kernel<<<(825000 + 255) / 256, 256>>>((const int*)ei, (const int*)bat, oddc);

    // edge conversion + degree histogram (fused)
    ei_hist_kernel<<<(N_EDGES + 255) / 256, 256>>>(ei, src, dst, oddc, degi);
    // batch conversion + dinv (fused)
    bat_dinv_kernel<<<(N_NODES + 255) / 256, 256>>>(bat, batch, oddc, degi, dinv);

    // CSR offsets
    scan1_kernel<<<SCAN_NB, SCAN_BLK>>>(degi, offs, parts);
    scan2_kernel<<<1, 32>>>(parts);
    scan3_kernel<<<(N_NODES + 255) / 256, 256>>>(offs, cursor, parts);
    scatter_build_kernel<<<(N_EDGES + 255) / 256, 256>>>(src, dst, cursor, ssrc);

    // weight transpose + fp16 (both weights, one kernel)
    conv_w_kernel<<<(HID * IN_CH + OUT_CH * HID + 255) / 256, 256>>>(W1, W2, w1t, w2t);

    // h1 = x @ W1  (fp16 HMMA, fp32 A rounded in-kernel, fp16 out)
    mma_gemm_kernel<HID, true><<<dim3(HID / 128, N_PAD / 128), 256>>>(x, w1t, h1);

    // layer-1 gather + ELU + bias -> fp16 a2
    gather_kernel<HID, 0><<<(N_NODES + 3) / 4, 128>>>(
        offs, degi, ssrc, dinv, h1, b1, a2, nullptr, nullptr, nullptr);

    // h2 = a2 @ W2  (fp16 HMMA, fp16 out)
    mma_gemm_kernel<OUT_CH, false><<<dim3(OUT_CH / 128, N_PAD / 128), 256>>>(a2, w2t, h2);

    // layer-2 gather + bias + mean-pool accumulate
    gather_kernel<OUT_CH, 1><<<(N_NODES + 3) / 4, 128>>>(
        offs, degi, ssrc, dinv, h2, b2, nullptr, batch, sums, counts);

    pool_final_kernel<<<(N_GRAPHS * OUT_CH + 255) / 256, 256>>>(sums, counts, out);
}

// round 11
// speedup vs baseline: 3.0143x; 1.0628x over previous
#include <cuda_runtime.h>
#include <cuda_fp16.h>
#include <cstdint>

#define N_NODES 50000
#define N_PAD   50048      // multiple of 128 for MMA tiles
#define N_EDGES 800000
#define IN_CH 256
#define HID 256
#define OUT_CH 128
#define N_GRAPHS 64
#define SCAN_BLK 512
#define SCAN_NB  ((N_NODES + SCAN_BLK - 1) / SCAN_BLK)   // 98

// ---------------- scratch (device globals; no cudaMalloc allowed) ----------
__device__ float g_dinv[N_NODES];
__device__ int   g_degi[N_NODES];
__device__ int   g_offs[N_NODES];
__device__ int   g_cursor[N_NODES];
__device__ int   g_partials[SCAN_NB];
__device__ int   g_ssrc[N_EDGES];
__device__ float g_swgt[N_EDGES];
__device__ __half g_h1[(size_t)N_PAD * HID];
__device__ __half g_h2[(size_t)N_PAD * OUT_CH];
__device__ float g_sums[N_GRAPHS * OUT_CH];
__device__ int   g_counts[N_GRAPHS];
__device__ int   g_src[N_EDGES];
__device__ int   g_dst[N_EDGES];
__device__ int   g_batch[N_NODES];
__device__ int   g_oddcnt[2];             // [0]=edge_index, [1]=batch
// fp16 operands. Pad rows (>= N_NODES) of g_a2 stay zero: zero-initialized
// device globals, never written.
__device__ __half g_a2[(size_t)N_PAD * HID];
__device__ __half g_w1t[HID * IN_CH];     // [n][k] = W1[k][n]
__device__ __half g_w2t[OUT_CH * HID];

// ---------------- helpers ---------------------------------------------------
__device__ __forceinline__ void red_add_v4(float* addr, float4 v) {
    asm volatile("red.global.add.v4.f32 [%0], {%1,%2,%3,%4};"
                 :: "l"(addr), "f"(v.x), "f"(v.y), "f"(v.z), "f"(v.w) : "memory");
}
__device__ __forceinline__ void mma_f16(float* c, uint32_t a0, uint32_t a1,
                                        uint32_t a2, uint32_t a3,
                                        uint32_t b0, uint32_t b1) {
    asm volatile("mma.sync.aligned.m16n8k16.row.col.f32.f16.f16.f32 "
                 "{%0,%1,%2,%3}, {%4,%5,%6,%7}, {%8,%9}, {%0,%1,%2,%3};"
                 : "+f"(c[0]), "+f"(c[1]), "+f"(c[2]), "+f"(c[3])
                 : "r"(a0), "r"(a1), "r"(a2), "r"(a3), "r"(b0), "r"(b1));
}
__device__ __forceinline__ uint32_t pack_h2(float a, float b) {
    __half2 h = __floats2half2_rn(a, b);
    return *reinterpret_cast<uint32_t*>(&h);
}

// ---------------- dtype detection (both buffers, one kernel) -----------------
__global__ void detect_kernel(const int* __restrict__ ei32, const int* __restrict__ bat32,
                              int* __restrict__ cnt) {
    int i = blockIdx.x * blockDim.x + threadIdx.x;
    int local = 0, which = -1;
    if (i < 800000)       { which = 0; local = (ei32[2 * i + 1] != 0); }
    else if (i < 825000)  { which = 1; local = (bat32[2 * (i - 800000) + 1] != 0); }
    unsigned m = __ballot_sync(0xFFFFFFFFu, local);
    if ((threadIdx.x & 31) == 0 && m && which >= 0) atomicAdd(&cnt[which], __popc(m));
}
// fused: edge conversion + degree histogram
__global__ void ei_hist_kernel(const void* __restrict__ ei, int* __restrict__ src,
                               int* __restrict__ dst, const int* __restrict__ cnt,
                               int* __restrict__ degi) {
    int e = blockIdx.x * blockDim.x + threadIdx.x;
    if (e >= N_EDGES) return;
    int s, d;
    if (cnt[0] < 100) { const long long* p = (const long long*)ei; s = (int)p[e]; d = (int)p[N_EDGES + e]; }
    else              { const int* p = (const int*)ei;             s = p[e];      d = p[N_EDGES + e]; }
    s = min(max(s, 0), N_NODES - 1);
    d = min(max(d, 0), N_NODES - 1);
    src[e] = s;
    dst[e] = d;
    atomicAdd(&degi[d], 1);
}
// fused: batch conversion + dinv
__global__ void bat_dinv_kernel(const void* __restrict__ bat, int* __restrict__ batch,
                                const int* __restrict__ cnt,
                                const int* __restrict__ degi, float* __restrict__ dinv) {
    int i = blockIdx.x * blockDim.x + threadIdx.x;
    if (i >= N_NODES) return;
    int g;
    if (cnt[1] < 100) g = (int)((const long long*)bat)[i];
    else              g = ((const int*)bat)[i];
    batch[i] = min(max(g, 0), N_GRAPHS - 1);
    dinv[i] = rsqrtf((float)degi[i] + 1.0f);
}

// ---------------- weight transpose + fp16 convert (both weights) -------------
__global__ void conv_w_kernel(const float* __restrict__ W1, const float* __restrict__ W2,
                              __half* __restrict__ w1t, __half* __restrict__ w2t) {
    int i = blockIdx.x * blockDim.x + threadIdx.x;
    if (i < HID * IN_CH) {
        int n = i / IN_CH, k = i % IN_CH;
        w1t[(size_t)n * IN_CH + k] = __float2half_rn(W1[(size_t)k * HID + n]);
    } else {
        int j = i - HID * IN_CH;
        if (j < OUT_CH * HID) {
            int n = j / HID, k = j % HID;
            w2t[(size_t)n * HID + k] = __float2half_rn(W2[(size_t)k * OUT_CH + n]);
        }
    }
}

// ---------------- CSR scan ----------------------------------------------------
__global__ __launch_bounds__(SCAN_BLK) void scan1_kernel(
    const int* __restrict__ degi, int* __restrict__ offs, int* __restrict__ partials) {
    __shared__ int sm[SCAN_BLK];
    int i = blockIdx.x * SCAN_BLK + threadIdx.x;
    int v = (i < N_NODES) ? degi[i] : 0;
    sm[threadIdx.x] = v;
    __syncthreads();
    for (int d = 1; d < SCAN_BLK; d <<= 1) {
        int t = (threadIdx.x >= d) ? sm[threadIdx.x - d] : 0;
        __syncthreads();
        sm[threadIdx.x] += t;
        __syncthreads();
    }
    if (i < N_NODES) offs[i] = sm[threadIdx.x] - v;       // exclusive
    if (threadIdx.x == SCAN_BLK - 1) partials[blockIdx.x] = sm[SCAN_BLK - 1];
}
// single-warp shfl scan over SCAN_NB partials (exclusive)
__global__ void scan2_kernel(int* __restrict__ partials) {
    int lane = threadIdx.x;
    int run = 0;
    for (int b = 0; b < SCAN_NB; b += 32) {
        int idx = b + lane;
        int orig = (idx < SCAN_NB) ? partials[idx] : 0;
        int v = orig;
        #pragma unroll
        for (int d = 1; d < 32; d <<= 1) {
            int t = __shfl_up_sync(0xFFFFFFFFu, v, d);
            if (lane >= d) v += t;
        }
        if (idx < SCAN_NB) partials[idx] = run + v - orig;   // exclusive
        run += __shfl_sync(0xFFFFFFFFu, v, 31);
    }
}
__global__ void scan3_kernel(int* __restrict__ offs, int* __restrict__ cursor,
                             const int* __restrict__ partials) {
    int i = blockIdx.x * blockDim.x + threadIdx.x;
    if (i < N_NODES) {
        int o = offs[i] + partials[i / SCAN_BLK];
        offs[i] = o;
        cursor[i] = o;
    }
}
// build sorted src + precomputed edge weight dinv[s]*dinv[d]
__global__ void scatter_build_kernel(const int* __restrict__ src, const int* __restrict__ dst,
                                     int* __restrict__ cursor, int* __restrict__ ssrc,
                                     float* __restrict__ swgt,
                                     const float* __restrict__ dinv) {
    int e = blockIdx.x * blockDim.x + threadIdx.x;
    if (e >= N_EDGES) return;
    int s = src[e], d = dst[e];
    int pos = atomicAdd(&cursor[d], 1);
    ssrc[pos] = s;
    swgt[pos] = dinv[s] * dinv[d];
}

// ---------------- HMMA GEMM: C[Mpad,NT] = A[Mpad,256] @ Wt[NT,256]^T --------
#define PADK 40
template <int NT, bool AFP32>
__global__ __launch_bounds__(256) void mma_gemm_kernel(
    const void* __restrict__ A_,
    const __half* __restrict__ B,
    __half* __restrict__ C)
{
    constexpr int K = 256;
    __shared__ __align__(16) __half sA[128 * PADK];
    __shared__ __align__(16) __half sB[128 * PADK];

    const int tid  = threadIdx.x;
    const int lane = tid & 31;
    const int wid  = tid >> 5;
    const int wm   = wid & 3;
    const int wn   = wid >> 2;
    const int bm   = blockIdx.y * 128;
    const int bn   = blockIdx.x * 128;

    const int r0l = tid >> 2, i0l = (tid & 3) * 8;
    const int r1l = r0l + 64;

    float acc[2][8][4];
    #pragma unroll
    for (int mt = 0; mt < 2; mt++)
        #pragma unroll
        for (int nt = 0; nt < 8; nt++)
            #pragma unroll
            for (int j = 0; j < 4; j++) acc[mt][nt][j] = 0.0f;

    const int qr = lane >> 2;
    const int qc = (lane & 3) * 2;

    float4 pAf[2][2];
    uint4  pA[2];
    uint4  pB[2];

    auto prefetch = [&](int kc) {
        if constexpr (AFP32) {
            const float* A = (const float*)A_;
            #pragma unroll
            for (int it = 0; it < 2; it++) {
                int r = (it == 0) ? r0l : r1l;
                if (bm + r < N_NODES) {
                    size_t gi = (size_t)(bm + r) * K + kc + i0l;
                    pAf[it][0] = *(const float4*)(A + gi);
                    pAf[it][1] = *(const float4*)(A + gi + 4);
                } else {
                    pAf[it][0] = make_float4(0.f, 0.f, 0.f, 0.f);
                    pAf[it][1] = make_float4(0.f, 0.f, 0.f, 0.f);
                }
            }
        } else {
            const __half* A = (const __half*)A_;
            #pragma unroll
            for (int it = 0; it < 2; it++) {
                int r = (it == 0) ? r0l : r1l;
                size_t gi = (size_t)(bm + r) * K + kc + i0l;
                pA[it] = *(const uint4*)(A + gi);
            }
        }
        #pragma unroll
        for (int it = 0; it < 2; it++) {
            int r = (it == 0) ? r0l : r1l;
            size_t gi = (size_t)(bn + r) * K + kc + i0l;
            pB[it] = *(const uint4*)(B + gi);
        }
    };

    auto stage = [&]() {
        if constexpr (AFP32) {
            #pragma unroll
            for (int it = 0; it < 2; it++) {
                int r = (it == 0) ? r0l : r1l;
                uint4 v;
                v.x = pack_h2(pAf[it][0].x, pAf[it][0].y);
                v.y = pack_h2(pAf[it][0].z, pAf[it][0].w);
                v.z = pack_h2(pAf[it][1].x, pAf[it][1].y);
                v.w = pack_h2(pAf[it][1].z, pAf[it][1].w);
                *(uint4*)&sA[r * PADK + i0l] = v;
            }
        } else {
            #pragma unroll
            for (int it = 0; it < 2; it++) {
                int r = (it == 0) ? r0l : r1l;
                *(uint4*)&sA[r * PADK + i0l] = pA[it];
            }
        }
        #pragma unroll
        for (int it = 0; it < 2; it++) {
            int r = (it == 0) ? r0l : r1l;
            *(uint4*)&sB[r * PADK + i0l] = pB[it];
        }
    };

    prefetch(0);
    for (int kc = 0; kc < K; kc += 32) {
        stage();
        __syncthreads();
        if (kc + 32 < K) prefetch(kc + 32);   // LDGs overlap with MMAs below

        #pragma unroll
        for (int ks = 0; ks < 2; ks++) {
            const int kb = ks * 16;
            uint32_t ah[2][4];
            #pragma unroll
            for (int mt = 0; mt < 2; mt++) {
                int rr = wm * 32 + mt * 16 + qr;
                #pragma unroll
                for (int h = 0; h < 2; h++) {
                    int r = rr + h * 8;
                    ah[mt][h]     = *(const uint32_t*)&sA[r * PADK + kb + qc];
                    ah[mt][h + 2] = *(const uint32_t*)&sA[r * PADK + kb + qc + 8];
                }
            }
            #pragma unroll
            for (int nt = 0; nt < 8; nt++) {
                int n = wn * 64 + nt * 8 + qr;
                uint32_t b0 = *(const uint32_t*)&sB[n * PADK + kb + qc];
                uint32_t b1 = *(const uint32_t*)&sB[n * PADK + kb + qc + 8];
                #pragma unroll
                for (int mt = 0; mt < 2; mt++)
                    mma_f16(acc[mt][nt], ah[mt][0], ah[mt][1], ah[mt][2], ah[mt][3],
                            b0, b1);
            }
        }
        __syncthreads();
    }

    #pragma unroll
    for (int mt = 0; mt < 2; mt++) {
        #pragma unroll
        for (int nt = 0; nt < 8; nt++) {
            int r0 = bm + wm * 32 + mt * 16 + qr;
            int c0 = bn + wn * 64 + nt * 8 + qc;
            *(uint32_t*)(C + (size_t)r0 * NT + c0) = pack_h2(acc[mt][nt][0], acc[mt][nt][1]);
            *(uint32_t*)(C + (size_t)(r0 + 8) * NT + c0) = pack_h2(acc[mt][nt][2], acc[mt][nt][3]);
        }
    }
}

// ---------------- CSR gather aggregation (fp16 features) ---------------------
// Warp per node. Per 32-edge chunk: two coalesced LDGs (indices + precomputed
// weights), shfl-broadcast per edge -> the only per-edge load is the h row.
// MODE 0 (layer 1, F=256): lane owns 8 cols (uint4);  out fp16 a2
// MODE 1 (layer 2, F=128): lane owns 4 cols (uint2);  red-add into sums
template <int F, int MODE>
__global__ __launch_bounds__(128) void gather_kernel(
    const int* __restrict__ offs, const int* __restrict__ degi,
    const int* __restrict__ ssrc, const float* __restrict__ swgt,
    const float* __restrict__ dinv,
    const __half* __restrict__ h, const float* __restrict__ bias,
    __half* __restrict__ oh,
    const int* __restrict__ batch, float* __restrict__ sums,
    int* __restrict__ counts)
{
    constexpr int HPL = F / 32;                   // halves per lane: 8 or 4
    int node = blockIdx.x * 4 + (threadIdx.x >> 5);
    int lane = threadIdx.x & 31;
    if (node >= N_NODES) return;

    int start = offs[node];
    int dg    = degi[node];
    float dn  = dinv[node];

    float acc[HPL];
    #pragma unroll
    for (int v = 0; v < HPL; v++) acc[v] = 0.0f;

    auto accum = [&](int s, float w) {
        if constexpr (HPL == 8) {
            uint4 v = __ldg((const uint4*)(h + (size_t)s * F) + lane);
            const __half2* hp = (const __half2*)&v;
            #pragma unroll
            for (int i = 0; i < 4; i++) {
                float2 f = __half22float2(hp[i]);
                acc[2 * i]     += w * f.x;
                acc[2 * i + 1] += w * f.y;
            }
        } else {
            uint2 v = __ldg((const uint2*)(h + (size_t)s * F) + lane);
            const __half2* hp = (const __half2*)&v;
            #pragma unroll
            for (int i = 0; i < 2; i++) {
                float2 f = __half22float2(hp[i]);
                acc[2 * i]     += w * f.x;
                acc[2 * i + 1] += w * f.y;
            }
        }
    };

    for (int base = 0; base < dg; base += 32) {
        int nch = min(32, dg - base);
        int   s_l = 0;
        float w_l = 0.0f;
        if (lane < nch) {
            s_l = __ldg(&ssrc[start + base + lane]);     // coalesced
            w_l = __ldg(&swgt[start + base + lane]);     // coalesced (precomputed)
        }
        #pragma unroll 4
        for (int j = 0; j < nch; j++) {
            int   s = __shfl_sync(0xFFFFFFFFu, s_l, j);
            float w = __shfl_sync(0xFFFFFFFFu, w_l, j);
            accum(s, w);                                 // independent h-row loads
        }
    }

    float sl = dn * dn;      // 1/deg (self-loop weight)
    int col = lane * HPL;
    float selfv[HPL];
    if constexpr (HPL == 8) {
        uint4 v = __ldg((const uint4*)(h + (size_t)node * F) + lane);
        const __half2* hp = (const __half2*)&v;
        #pragma unroll
        for (int i = 0; i < 4; i++) {
            float2 f = __half22float2(hp[i]);
            selfv[2 * i] = f.x; selfv[2 * i + 1] = f.y;
        }
    } else {
        uint2 v = __ldg((const uint2*)(h + (size_t)node * F) + lane);
        const __half2* hp = (const __half2*)&v;
        #pragma unroll
        for (int i = 0; i < 2; i++) {
            float2 f = __half22float2(hp[i]);
            selfv[2 * i] = f.x; selfv[2 * i + 1] = f.y;
        }
    }

    if constexpr (MODE == 0) {
        uint32_t outw[HPL / 2];
        #pragma unroll
        for (int i = 0; i < HPL; i += 2) {
            float r0 = acc[i]     + selfv[i]     * sl + bias[col + i];
            float r1 = acc[i + 1] + selfv[i + 1] * sl + bias[col + i + 1];
            r0 = r0 > 0.f ? r0 : expm1f(r0);
            r1 = r1 > 0.f ? r1 : expm1f(r1);
            outw[i / 2] = pack_h2(r0, r1);
        }
        *(uint4*)(oh + (size_t)node * F + col) =
            make_uint4(outw[0], outw[1], outw[2], outw[3]);
    } else {
        int g = batch[node];
        float4 bv = *(const float4*)(bias + col);
        float4 r = make_float4(acc[0] + selfv[0] * sl + bv.x,
                               acc[1] + selfv[1] * sl + bv.y,
                               acc[2] + selfv[2] * sl + bv.z,
                               acc[3] + selfv[3] * sl + bv.w);
        red_add_v4(sums + g * F + col, r);
        if (lane == 0) atomicAdd(&counts[g], 1);
    }
}

__global__ void pool_final_kernel(const float* __restrict__ sums,
                                  const int* __restrict__ counts,
                                  float* __restrict__ out)
{
    int c = blockIdx.x * blockDim.x + threadIdx.x;
    if (c < N_GRAPHS * OUT_CH) {
        int g = c / OUT_CH;
        float cnt = fmaxf((float)counts[g], 1.0f);
        out[c] = sums[c] / cnt;
    }
}

__global__ void zero_out_kernel(float* out, int n) {
    int i = blockIdx.x * blockDim.x + threadIdx.x;
    if (i < n) out[i] = 0.0f;
}

// ---------------- launch -----------------------------------------------------
extern "C" void kernel_launch(void* const* d_in, const int* in_sizes, int n_in,
                              void* d_out, int out_size)
{
    const float* x   = nullptr;
    const float* W1  = nullptr;
    const float* b1  = nullptr;
    const float* W2  = nullptr;
    const float* b2  = nullptr;
    const void*  ei  = nullptr;
    const void*  bat = nullptr;

    for (int i = 0; i < n_in; i++) {
        switch (in_sizes[i]) {
            case 12800000: x   = (const float*)d_in[i]; break;
            case 65536:    W1  = (const float*)d_in[i]; break;
            case 256:      b1  = (const float*)d_in[i]; break;
            case 32768:    W2  = (const float*)d_in[i]; break;
            case 128:      b2  = (const float*)d_in[i]; break;
            case 1600000:  ei  = d_in[i];               break;
            case 50000:    bat = d_in[i];               break;
            default: break;
        }
    }
    float* out = (float*)d_out;

    if (!x || !W1 || !b1 || !W2 || !b2 || !ei || !bat) {
        zero_out_kernel<<<(out_size + 255) / 256, 256>>>(out, out_size);
        return;
    }

    void* p;
    cudaGetSymbolAddress(&p, g_dinv);    float* dinv   = (float*)p;
    cudaGetSymbolAddress(&p, g_degi);    int*   degi   = (int*)p;
    cudaGetSymbolAddress(&p, g_offs);    int*   offs   = (int*)p;
    cudaGetSymbolAddress(&p, g_cursor);  int*   cursor = (int*)p;
    cudaGetSymbolAddress(&p, g_partials);int*   parts  = (int*)p;
    cudaGetSymbolAddress(&p, g_ssrc);    int*   ssrc   = (int*)p;
    cudaGetSymbolAddress(&p, g_swgt);    float* swgt   = (float*)p;
    cudaGetSymbolAddress(&p, g_h1);      __half* h1    = (__half*)p;
    cudaGetSymbolAddress(&p, g_h2);      __half* h2    = (__half*)p;
    cudaGetSymbolAddress(&p, g_sums);    float* sums   = (float*)p;
    cudaGetSymbolAddress(&p, g_counts);  int*   counts = (int*)p;
    cudaGetSymbolAddress(&p, g_src);     int*   src    = (int*)p;
    cudaGetSymbolAddress(&p, g_dst);     int*   dst    = (int*)p;
    cudaGetSymbolAddress(&p, g_batch);   int*   batch  = (int*)p;
    cudaGetSymbolAddress(&p, g_oddcnt);  int*   oddc   = (int*)p;
    cudaGetSymbolAddress(&p, g_a2);      __half* a2    = (__half*)p;
    cudaGetSymbolAddress(&p, g_w1t);     __half* w1t   = (__half*)p;
    cudaGetSymbolAddress(&p, g_w2t);     __half* w2t   = (__half*)p;

    // static host-side resources (streams/events are NOT device memory)
    static cudaStream_t s2 = nullptr;
    static cudaEvent_t evFork = nullptr, evJoin = nullptr;
    if (!s2) {
        cudaStreamCreateWithFlags(&s2, cudaStreamNonBlocking);
        cudaEventCreateWithFlags(&evFork, cudaEventDisableTiming);
        cudaEventCreateWithFlags(&evJoin, cudaEventDisableTiming);
    }

    // ---- fork: weights + GEMM1 on s2, independent of the CSR chain ----
    cudaEventRecord(evFork, 0);
    cudaStreamWaitEvent(s2, evFork, 0);

    conv_w_kernel<<<(HID * IN_CH + OUT_CH * HID + 255) / 256, 256, 0, s2>>>(
        W1, W2, w1t, w2t);
    mma_gemm_kernel<HID, true><<<dim3(HID / 128, N_PAD / 128), 256, 0, s2>>>(
        x, w1t, h1);
    cudaEventRecord(evJoin, s2);

    // ---- main stream: CSR build chain ----
    cudaMemsetAsync(degi,   0, N_NODES * sizeof(int));
    cudaMemsetAsync(sums,   0, N_GRAPHS * OUT_CH * sizeof(float));
    cudaMemsetAsync(counts, 0, N_GRAPHS * sizeof(int));
    cudaMemsetAsync(oddc,   0, 2 * sizeof(int));

    detect_kernel<<<(825000 + 255) / 256, 256>>>((const int*)ei, (const int*)bat, oddc);
    ei_hist_kernel<<<(N_EDGES + 255) / 256, 256>>>(ei, src, dst, oddc, degi);
    bat_dinv_kernel<<<(N_NODES + 255) / 256, 256>>>(bat, batch, oddc, degi, dinv);
    scan1_kernel<<<SCAN_NB, SCAN_BLK>>>(degi, offs, parts);
    scan2_kernel<<<1, 32>>>(parts);
    scan3_kernel<<<(N_NODES + 255) / 256, 256>>>(offs, cursor, parts);
    scatter_build_kernel<<<(N_EDGES + 255) / 256, 256>>>(src, dst, cursor, ssrc, swgt, dinv);

    // ---- join: gather1 needs both h1 (s2) and CSR (main) ----
    cudaStreamWaitEvent(0, evJoin, 0);

    gather_kernel<HID, 0><<<(N_NODES + 3) / 4, 128>>>(
        offs, degi, ssrc, swgt, dinv, h1, b1, a2, nullptr, nullptr, nullptr);

    mma_gemm_kernel<OUT_CH, false><<<dim3(OUT_CH / 128, N_PAD / 128), 256>>>(a2, w2t, h2);

    gather_kernel<OUT_CH, 1><<<(N_NODES + 3) / 4, 128>>>(
        offs, degi, ssrc, swgt, dinv, h2, b2, nullptr, batch, sums, counts);

    pool_final_kernel<<<(N_GRAPHS * OUT_CH + 255) / 256, 256>>>(sums, counts, out);
}